// round 16
// baseline (speedup 1.0000x reference)
#include <cuda_runtime.h>
#include <cuda_bf16.h>
#include <math.h>

#define Bb 2
#define Ls 2048
#define Ds 1024
#define Hh 16
#define HDd 64
#define FFs 4096
#define BLn (Bb*Ls)
#define EPSf 1e-5f

// ---------------- scratch (static device memory) ----------------
__device__ float g_stage[BLn*Ds];
__device__ float g_kst[BLn*Ds];
__device__ float g_v[BLn*Ds];
__device__ float g_tgt2[BLn*Ds];
__device__ float g_mem[BLn*Ds];
__device__ float g_h2[BLn*2*Ds];
__device__ float g_conv[BLn*Ds];
__device__ float g_mem2[BLn*Ds];
__device__ float g_sum[BLn*Ds];
__device__ unsigned short g_ah[16777216];
__device__ unsigned short g_al[16777216];
__device__ unsigned short g_ch[16777216];
__device__ unsigned short g_cl[16777216];
#define OFF_WQ    0
#define OFF_WK    1048576
#define OFF_WV    2097152
#define OFF_WO    3145728
#define OFF_PW1   4194304
#define OFF_PW2   6291456
#define OFF_PROJ2 7340032
#define OFF_LIN1  8388608
#define OFF_LIN2  12582912
#define OFF_PROJT 16777216
__device__ unsigned short g_wh[20971520];
__device__ unsigned short g_wl[20971520];
__device__ unsigned short g_qh2[4194304];
__device__ unsigned short g_ql2[4194304];
__device__ unsigned short g_kh2[4194304];
__device__ unsigned short g_kl2[4194304];
__device__ unsigned short g_vh2[4194304];
__device__ unsigned short g_vl2[4194304];

// ---------------- helpers ----------------
__device__ __forceinline__ float fexp(float x)
{
    float t = x * 1.442695041f;
    t = fmaxf(t, -126.f);
    float fn = t + 12582912.f;
    int n = __float_as_int(fn) - 0x4B400000;
    float f = t - (fn - 12582912.f);
    float p = 1.33335581e-3f;
    p = fmaf(p, f, 9.61812910e-3f);
    p = fmaf(p, f, 5.55041087e-2f);
    p = fmaf(p, f, 2.40226507e-1f);
    p = fmaf(p, f, 6.93147180e-1f);
    p = fmaf(p, f, 1.0f);
    return __int_as_float((n + 127) << 23) * p;
}

__device__ __forceinline__ float gelu_exact(float v)
{
    return 0.5f * v * (1.f + erff(v * 0.70710678118654752f));
}

__device__ __forceinline__ void split2(float v, unsigned short& h, unsigned short& l)
{
    __nv_bfloat16 hb = __float2bfloat16_rn(v);
    h = __bfloat16_as_ushort(hb);
    l = __bfloat16_as_ushort(__float2bfloat16_rn(v - __bfloat162float(hb)));
}

// ---------------- mega split ----------------
__global__ __launch_bounds__(256) void mega_split_kernel(
    const float* __restrict__ wq, const float* __restrict__ wk,
    const float* __restrict__ wv, const float* __restrict__ wo,
    const float* __restrict__ pw1, const float* __restrict__ pw2,
    const float* __restrict__ proj2, const float* __restrict__ lin1,
    const float* __restrict__ lin2, const float* __restrict__ memory,
    unsigned short* __restrict__ wh, unsigned short* __restrict__ wl,
    unsigned short* __restrict__ ah, unsigned short* __restrict__ al)
{
    long i4 = (long)blockIdx.x * 256 + threadIdx.x;
    if (i4 >= 5242880L) return;
    const float* src;
    unsigned short* dh;
    unsigned short* dl;
    if (i4 < 4194304L) {
        const float* s;
        long bse;
        if (i4 < 262144L) { s = wq; bse = 0; }
        else if (i4 < 524288L) { s = wk; bse = 262144L; }
        else if (i4 < 786432L) { s = wv; bse = 524288L; }
        else if (i4 < 1048576L) { s = wo; bse = 786432L; }
        else if (i4 < 1572864L) { s = pw1; bse = 1048576L; }
        else if (i4 < 1835008L) { s = pw2; bse = 1572864L; }
        else if (i4 < 2097152L) { s = proj2; bse = 1835008L; }
        else if (i4 < 3145728L) { s = lin1; bse = 2097152L; }
        else { s = lin2; bse = 3145728L; }
        src = s + (i4 - bse) * 4;
        dh = wh + i4 * 4;
        dl = wl + i4 * 4;
    } else {
        long r = i4 - 4194304L;
        src = memory + r * 4;
        dh = ah + r * 4;
        dl = al + r * 4;
    }
    float4 v = *(const float4*)src;
    ushort4 hv, lv;
    split2(v.x, hv.x, lv.x);
    split2(v.y, hv.y, lv.y);
    split2(v.z, hv.z, lv.z);
    split2(v.w, hv.w, lv.w);
    *(ushort4*)dh = hv;
    *(ushort4*)dl = lv;
}

// ---------------- transpose + split ----------------
__global__ __launch_bounds__(256) void splitT_kernel(
    const float* __restrict__ in, unsigned short* __restrict__ hiT,
    unsigned short* __restrict__ loT, int R, int C, long sz)
{
    __shared__ float t[32][33];
    const float* inz = in + (long)blockIdx.z * sz;
    unsigned short* hz = hiT + (long)blockIdx.z * sz;
    unsigned short* lz = loT + (long)blockIdx.z * sz;
    int tx = threadIdx.x, ty = threadIdx.y;
    int x = blockIdx.x * 32 + tx;
    int y0 = blockIdx.y * 32;
#pragma unroll
    for (int j = 0; j < 32; j += 8)
        t[ty + j][tx] = inz[(long)(y0 + ty + j) * C + x];
    __syncthreads();
    int ox = blockIdx.y * 32 + tx;
    int oy0 = blockIdx.x * 32;
#pragma unroll
    for (int j = 0; j < 32; j += 8) {
        float val = t[tx][ty + j];
        unsigned short h, l;
        split2(val, h, l);
        hz[(long)(oy0 + ty + j) * R + ox] = h;
        lz[(long)(oy0 + ty + j) * R + ox] = l;
    }
}

// ---------------- mma helpers ----------------
__device__ __forceinline__ unsigned smem_u32(const void* p)
{
    return (unsigned)__cvta_generic_to_shared(p);
}
__device__ __forceinline__ void cp16(unsigned s, const void* g)
{
    asm volatile("cp.async.cg.shared.global [%0], [%1], 16;" :: "r"(s), "l"(g));
}
__device__ __forceinline__ void cp_commit()
{
    asm volatile("cp.async.commit_group;");
}
__device__ __forceinline__ void cp_wait1()
{
    asm volatile("cp.async.wait_group 1;");
}
__device__ __forceinline__ void cp_wait0()
{
    asm volatile("cp.async.wait_group 0;");
}
__device__ __forceinline__ void ldsm4(unsigned& r0, unsigned& r1, unsigned& r2, unsigned& r3, unsigned a)
{
    asm volatile("ldmatrix.sync.aligned.m8n8.x4.shared.b16 {%0,%1,%2,%3}, [%4];"
        : "=r"(r0), "=r"(r1), "=r"(r2), "=r"(r3) : "r"(a));
}
__device__ __forceinline__ void ldsm2(unsigned& r0, unsigned& r1, unsigned a)
{
    asm volatile("ldmatrix.sync.aligned.m8n8.x2.shared.b16 {%0,%1}, [%2];"
        : "=r"(r0), "=r"(r1) : "r"(a));
}
__device__ __forceinline__ void ldsm2t(unsigned& r0, unsigned& r1, unsigned a)
{
    asm volatile("ldmatrix.sync.aligned.m8n8.x2.trans.shared.b16 {%0,%1}, [%2];"
        : "=r"(r0), "=r"(r1) : "r"(a));
}
__device__ __forceinline__ void mma16816(float* d, const unsigned* a, const unsigned* b)
{
    asm volatile("mma.sync.aligned.m16n8k16.row.col.f32.bf16.bf16.f32 "
        "{%0,%1,%2,%3}, {%4,%5,%6,%7}, {%8,%9}, {%0,%1,%2,%3};"
        : "+f"(d[0]), "+f"(d[1]), "+f"(d[2]), "+f"(d[3])
        : "r"(a[0]), "r"(a[1]), "r"(a[2]), "r"(a[3]), "r"(b[0]), "r"(b[1]));
}

// ---------------- bf16-split tensor-core GEMM (R12 proven + 3-pass mma ordering) ----------------
// CTA 128x128x32, 256 threads (8 warps: 2M x 4N), warp tile 64x32.
#define LDA_P 40
#define LDB_P 136
#define OFF_AL (128*40)
#define OFF_BH (2*128*40)
#define OFF_BL (2*128*40 + 32*136)
#define STAGE_ELEMS (2*128*40 + 2*32*136)
#define BG_SMEM_BYTES (3*STAGE_ELEMS*2)

__device__ __forceinline__ void bg_load_chunk(
    unsigned short* st,
    const unsigned short* __restrict__ Ah, const unsigned short* __restrict__ Al,
    const unsigned short* __restrict__ Bh, const unsigned short* __restrict__ Bl,
    int K, int N, int bm, int bn, int k0, int tid)
{
    const int ar0 = tid >> 1;
    const int ac0 = (tid & 1) * 16;
    const int br0 = tid >> 4;
    const int bc0 = (tid & 15) * 8;
    {
        long ga = (long)(bm + ar0) * K + k0 + ac0;
        cp16(smem_u32(st + ar0 * LDA_P + ac0), Ah + ga);
        cp16(smem_u32(st + ar0 * LDA_P + ac0 + 8), Ah + ga + 8);
        cp16(smem_u32(st + OFF_AL + ar0 * LDA_P + ac0), Al + ga);
        cp16(smem_u32(st + OFF_AL + ar0 * LDA_P + ac0 + 8), Al + ga + 8);
    }
    {
        long gb0 = (long)(k0 + br0) * N + bn + bc0;
        long gb1 = (long)(k0 + br0 + 16) * N + bn + bc0;
        cp16(smem_u32(st + OFF_BH + br0 * LDB_P + bc0), Bh + gb0);
        cp16(smem_u32(st + OFF_BH + (br0 + 16) * LDB_P + bc0), Bh + gb1);
        cp16(smem_u32(st + OFF_BL + br0 * LDB_P + bc0), Bl + gb0);
        cp16(smem_u32(st + OFF_BL + (br0 + 16) * LDB_P + bc0), Bl + gb1);
    }
    cp_commit();
}

__global__ __launch_bounds__(256, 1) void bgemm_kernel(
    const unsigned short* __restrict__ Ah, const unsigned short* __restrict__ Al,
    const unsigned short* __restrict__ Bh, const unsigned short* __restrict__ Bl,
    const float* __restrict__ bias, const float* __restrict__ addp,
    float* __restrict__ C, unsigned short* __restrict__ oh,
    unsigned short* __restrict__ ol, int M, int N, int K,
    long sB, long sC, int bias_mode, int act)
{
    extern __shared__ unsigned short smem[];
    const int tid = threadIdx.x;
    const int lane = tid & 31;
    const int warp = tid >> 5;
    const int bm = blockIdx.y * 128;
    const int bn = blockIdx.x * 128;
    const unsigned short* Bhz = Bh + (long)blockIdx.z * sB;
    const unsigned short* Blz = Bl + (long)blockIdx.z * sB;
    float* Cz = C ? (C + (long)blockIdx.z * sC) : (float*)0;
    unsigned short* ohz = oh ? (oh + (long)blockIdx.z * sC) : (unsigned short*)0;
    unsigned short* olz = ol ? (ol + (long)blockIdx.z * sC) : (unsigned short*)0;
    const float* addz = addp ? (addp + (long)blockIdx.z * sC) : (const float*)0;
    const int m0 = (warp & 1) * 64;
    const int n0 = (warp >> 1) * 32;

    float acc[4][4][4];
#pragma unroll
    for (int mi = 0; mi < 4; mi++)
#pragma unroll
        for (int ni = 0; ni < 4; ni++)
#pragma unroll
            for (int qq = 0; qq < 4; qq++) acc[mi][ni][qq] = 0.f;

    const int nIter = K >> 5;

    bg_load_chunk(smem, Ah, Al, Bhz, Blz, K, N, bm, bn, 0, tid);
    if (nIter > 1)
        bg_load_chunk(smem + STAGE_ELEMS, Ah, Al, Bhz, Blz, K, N, bm, bn, 32, tid);

#pragma unroll 1
    for (int it = 0; it < nIter; ++it) {
        if (it + 1 < nIter) cp_wait1(); else cp_wait0();
        __syncthreads();

        unsigned short* cur = smem + (it % 3) * STAGE_ELEMS;
#pragma unroll
        for (int ks = 0; ks < 32; ks += 16) {
            unsigned afh[4][4], afl[4][4], bfh[4][2], bfl[4][2];
#pragma unroll
            for (int mi = 0; mi < 4; mi++) {
                int row = m0 + mi * 16 + (lane & 15);
                int col = ks + (lane >> 4) * 8;
                ldsm4(afh[mi][0], afh[mi][1], afh[mi][2], afh[mi][3],
                      smem_u32(cur + row * LDA_P + col));
                ldsm4(afl[mi][0], afl[mi][1], afl[mi][2], afl[mi][3],
                      smem_u32(cur + OFF_AL + row * LDA_P + col));
            }
#pragma unroll
            for (int ni = 0; ni < 4; ni++) {
                int row = ks + (lane & 15);
                int col = n0 + ni * 8;
                ldsm2t(bfh[ni][0], bfh[ni][1], smem_u32(cur + OFF_BH + row * LDB_P + col));
                ldsm2t(bfl[ni][0], bfl[ni][1], smem_u32(cur + OFF_BL + row * LDB_P + col));
            }
            // 3-pass ordering: consecutive mmas hit distinct accumulators
            // (per-accumulator order hh,hl,lh unchanged -> bit-exact)
#pragma unroll
            for (int mi = 0; mi < 4; mi++)
#pragma unroll
                for (int ni = 0; ni < 4; ni++)
                    mma16816(acc[mi][ni], afh[mi], bfh[ni]);
#pragma unroll
            for (int mi = 0; mi < 4; mi++)
#pragma unroll
                for (int ni = 0; ni < 4; ni++)
                    mma16816(acc[mi][ni], afh[mi], bfl[ni]);
#pragma unroll
            for (int mi = 0; mi < 4; mi++)
#pragma unroll
                for (int ni = 0; ni < 4; ni++)
                    mma16816(acc[mi][ni], afl[mi], bfh[ni]);
        }
        if (it + 2 < nIter)
            bg_load_chunk(smem + ((it + 2) % 3) * STAGE_ELEMS,
                          Ah, Al, Bhz, Blz, K, N, bm, bn, (it + 2) << 5, tid);
    }

    const int r4 = lane >> 2;
    const int c2 = (lane & 3) * 2;
#pragma unroll
    for (int mi = 0; mi < 4; mi++) {
#pragma unroll
        for (int ni = 0; ni < 4; ni++) {
            int col = bn + n0 + ni * 8 + c2;
#pragma unroll
            for (int hf = 0; hf < 2; hf++) {
                int row = bm + m0 + mi * 16 + r4 + hf * 8;
                float v0 = acc[mi][ni][hf * 2 + 0];
                float v1 = acc[mi][ni][hf * 2 + 1];
                if (bias_mode == 1) { v0 += bias[col]; v1 += bias[col + 1]; }
                if (bias_mode == 2) { float bv = bias[row]; v0 += bv; v1 += bv; }
                if (addz) {
                    v0 += addz[(long)row * N + col];
                    v1 += addz[(long)row * N + col + 1];
                }
                if (act == 1) { v0 = gelu_exact(v0); v1 = gelu_exact(v1); }
                long idx = (long)row * N + col;
                if (Cz) {
                    float2 ov;
                    ov.x = v0; ov.y = v1;
                    *(float2*)(Cz + idx) = ov;
                }
                if (ohz) {
                    ushort2 hv, lv;
                    split2(v0, hv.x, lv.x);
                    split2(v1, hv.y, lv.y);
                    *(ushort2*)(ohz + idx) = hv;
                    *(ushort2*)(olz + idx) = lv;
                }
            }
        }
    }
}

// ---------------- clone with broadcast-row0 add (pw2 only) ----------------
__global__ __launch_bounds__(256, 1) void bgemm_brc_kernel(
    const unsigned short* __restrict__ Ah, const unsigned short* __restrict__ Al,
    const unsigned short* __restrict__ Bh, const unsigned short* __restrict__ Bl,
    const float* __restrict__ bias, const float* __restrict__ brc,
    float* __restrict__ C, int M, int N, int K)
{
    extern __shared__ unsigned short smem[];
    const int tid = threadIdx.x;
    const int lane = tid & 31;
    const int warp = tid >> 5;
    const int bm = blockIdx.y * 128;
    const int bn = blockIdx.x * 128;
    const int m0 = (warp & 1) * 64;
    const int n0 = (warp >> 1) * 32;

    float acc[4][4][4];
#pragma unroll
    for (int mi = 0; mi < 4; mi++)
#pragma unroll
        for (int ni = 0; ni < 4; ni++)
#pragma unroll
            for (int qq = 0; qq < 4; qq++) acc[mi][ni][qq] = 0.f;

    const int nIter = K >> 5;
    bg_load_chunk(smem, Ah, Al, Bh, Bl, K, N, bm, bn, 0, tid);
    if (nIter > 1)
        bg_load_chunk(smem + STAGE_ELEMS, Ah, Al, Bh, Bl, K, N, bm, bn, 32, tid);

#pragma unroll 1
    for (int it = 0; it < nIter; ++it) {
        if (it + 1 < nIter) cp_wait1(); else cp_wait0();
        __syncthreads();

        unsigned short* cur = smem + (it % 3) * STAGE_ELEMS;
#pragma unroll
        for (int ks = 0; ks < 32; ks += 16) {
            unsigned afh[4][4], afl[4][4], bfh[4][2], bfl[4][2];
#pragma unroll
            for (int mi = 0; mi < 4; mi++) {
                int row = m0 + mi * 16 + (lane & 15);
                int col = ks + (lane >> 4) * 8;
                ldsm4(afh[mi][0], afh[mi][1], afh[mi][2], afh[mi][3],
                      smem_u32(cur + row * LDA_P + col));
                ldsm4(afl[mi][0], afl[mi][1], afl[mi][2], afl[mi][3],
                      smem_u32(cur + OFF_AL + row * LDA_P + col));
            }
#pragma unroll
            for (int ni = 0; ni < 4; ni++) {
                int row = ks + (lane & 15);
                int col = n0 + ni * 8;
                ldsm2t(bfh[ni][0], bfh[ni][1], smem_u32(cur + OFF_BH + row * LDB_P + col));
                ldsm2t(bfl[ni][0], bfl[ni][1], smem_u32(cur + OFF_BL + row * LDB_P + col));
            }
#pragma unroll
            for (int mi = 0; mi < 4; mi++)
#pragma unroll
                for (int ni = 0; ni < 4; ni++)
                    mma16816(acc[mi][ni], afh[mi], bfh[ni]);
#pragma unroll
            for (int mi = 0; mi < 4; mi++)
#pragma unroll
                for (int ni = 0; ni < 4; ni++)
                    mma16816(acc[mi][ni], afh[mi], bfl[ni]);
#pragma unroll
            for (int mi = 0; mi < 4; mi++)
#pragma unroll
                for (int ni = 0; ni < 4; ni++)
                    mma16816(acc[mi][ni], afl[mi], bfh[ni]);
        }
        if (it + 2 < nIter)
            bg_load_chunk(smem + ((it + 2) % 3) * STAGE_ELEMS,
                          Ah, Al, Bh, Bl, K, N, bm, bn, (it + 2) << 5, tid);
    }

    const int r4 = lane >> 2;
    const int c2 = (lane & 3) * 2;
#pragma unroll
    for (int mi = 0; mi < 4; mi++) {
#pragma unroll
        for (int ni = 0; ni < 4; ni++) {
            int col = bn + n0 + ni * 8 + c2;
#pragma unroll
            for (int hf = 0; hf < 2; hf++) {
                int row = bm + m0 + mi * 16 + r4 + hf * 8;
                long bidx = (long)(row >> 11) * Ls * N + col;
                float v0 = acc[mi][ni][hf * 2 + 0] + bias[col] + brc[bidx];
                float v1 = acc[mi][ni][hf * 2 + 1] + bias[col + 1] + brc[bidx + 1];
                long idx = (long)row * N + col;
                float2 ov;
                ov.x = v0; ov.y = v1;
                *(float2*)(C + idx) = ov;
            }
        }
    }
}

// ---------------- rope helpers ----------------
__device__ __forceinline__ float rope_pval(int l, int m)
{
    int i = (m < 32) ? m : m - 32;
    float inv = powf(10000.f, -(float)(2 * i) / 64.f);
    float ang = (float)l * inv;
    return (m < 32) ? cosf(ang) : sinf(ang);
}

__device__ __forceinline__ void rope_body(const float* __restrict__ in,
    unsigned short* __restrict__ oh, unsigned short* __restrict__ ol, int idx)
{
    int j = idx & 31;
    int h = (idx >> 5) & 15;
    int bl = idx >> 9;
    int l = bl & (Ls - 1);
    int b = bl >> 11;
    long ibase = (long)bl * Ds + h * HDd;
    float xe = in[ibase + 2 * j];
    float xo = in[ibase + 2 * j + 1];
    float c = rope_pval(l, 2 * j);
    float s = rope_pval(l, 2 * j + 1);
    float y0 = xe * c - xo * s;
    float y1 = xe * s + xo * c;
    long obase = ((long)(b * Hh + h) * Ls + l) * HDd;
    unsigned short h0, l0, h1, l1;
    split2(y0, h0, l0);
    split2(y1, h1, l1);
    oh[obase + j] = h0;
    oh[obase + 32 + j] = h1;
    ol[obase + j] = l0;
    ol[obase + 32 + j] = l1;
}

__global__ __launch_bounds__(256) void qkv_post_kernel(
    const float* __restrict__ qs, const float* __restrict__ ks, const float* __restrict__ vs,
    unsigned short* __restrict__ qh, unsigned short* __restrict__ ql,
    unsigned short* __restrict__ kh, unsigned short* __restrict__ kl,
    unsigned short* __restrict__ vh, unsigned short* __restrict__ vl)
{
    int bid = blockIdx.x;
    int tid = threadIdx.x;
    if (bid < 8192) {
        rope_body(qs, qh, ql, bid * 256 + tid);
    } else if (bid < 16384) {
        rope_body(ks, kh, kl, (bid - 8192) * 256 + tid);
    } else {
        long idx4 = (long)(bid - 16384) * 256 + tid;
        int d4 = (int)(idx4 & 15);
        int h = (int)((idx4 >> 4) & 15);
        long l = (idx4 >> 8) & (Ls - 1);
        long b = idx4 >> 19;
        float4 v = *(const float4*)(vs + ((b * Ls + l) * Ds + h * HDd + d4 * 4));
        long o = ((b * Hh + h) * Ls + l) * HDd + d4 * 4;
        ushort4 hv, lv;
        split2(v.x, hv.x, lv.x);
        split2(v.y, hv.y, lv.y);
        split2(v.z, hv.z, lv.z);
        split2(v.w, hv.w, lv.w);
        *(ushort4*)(vh + o) = hv;
        *(ushort4*)(vl + o) = lv;
    }
}

// ---------------- tensor-core flash attention (R7 proven, UNTOUCHED) ----------------
#define AT2_QH 0
#define AT2_QL 9216
#define AT2_PH 18432
#define AT2_PL 27648
#define AT2_STG 36864
#define AT2_KH 0
#define AT2_KL 4608
#define AT2_VH 9216
#define AT2_VL 13824
#define AT2_STGSZ 18432
#define AT2_SMEM_BYTES ((36864 + 2*18432)*2)

__device__ __forceinline__ void at2_load_kv(
    unsigned sbase, int stage, int k0,
    const unsigned short* kh, const unsigned short* kl,
    const unsigned short* vh, const unsigned short* vl, int bh, int tid)
{
    unsigned so = (unsigned)(AT2_STG + stage * AT2_STGSZ);
#pragma unroll
    for (int i = 0; i < 2; i++) {
        int c = tid * 2 + i;
        int r = c >> 3;
        int cc = (c & 7) * 8;
        long g = ((long)bh * Ls + k0 + r) * HDd + cc;
        cp16(sbase + (so + AT2_KH + r * 72 + cc) * 2, kh + g);
        cp16(sbase + (so + AT2_KL + r * 72 + cc) * 2, kl + g);
        cp16(sbase + (so + AT2_VH + r * 72 + cc) * 2, vh + g);
        cp16(sbase + (so + AT2_VL + r * 72 + cc) * 2, vl + g);
    }
    cp_commit();
}

__global__ __launch_bounds__(256, 1) void attn2_kernel(
    const unsigned short* __restrict__ qh, const unsigned short* __restrict__ ql,
    const unsigned short* __restrict__ kh, const unsigned short* __restrict__ kl,
    const unsigned short* __restrict__ vh, const unsigned short* __restrict__ vl,
    unsigned short* __restrict__ Oh, unsigned short* __restrict__ Ol)
{
    extern __shared__ __align__(16) unsigned short sm2[];
    const int tid = threadIdx.x;
    const int lane = tid & 31;
    const int warp = tid >> 5;
    const int g = lane >> 2;
    const int tk = lane & 3;
    const int m0 = warp * 16;
    const int q0 = blockIdx.x * 128;
    const int bh = blockIdx.y;
    const int b = bh >> 4, h = bh & 15;
    const float slope = exp2f(-0.5f * (float)h);
    const unsigned sbase = smem_u32(sm2);

#pragma unroll
    for (int i = 0; i < 4; i++) {
        int t = tid + i * 256;
        int r = t >> 3;
        int cc = (t & 7) * 8;
        long gq = ((long)bh * Ls + q0 + r) * HDd + cc;
        cp16(sbase + (AT2_QH + r * 72 + cc) * 2, qh + gq);
        cp16(sbase + (AT2_QL + r * 72 + cc) * 2, ql + gq);
    }
    at2_load_kv(sbase, 0, 0, kh, kl, vh, vl, bh, tid);
    at2_load_kv(sbase, 1, 64, kh, kl, vh, vl, bh, tid);

    float acc_o[8][4];
#pragma unroll
    for (int dt = 0; dt < 8; dt++)
#pragma unroll
        for (int q = 0; q < 4; q++) acc_o[dt][q] = 0.f;
    float mstA = -1e30f, mstB = -1e30f, lstA = 0.f, lstB = 0.f;

    const int nc = Ls / 64;
#pragma unroll 1
    for (int it = 0; it < nc; ++it) {
        if (it < nc - 1) cp_wait1(); else cp_wait0();
        __syncthreads();
        unsigned so = (unsigned)(AT2_STG + (it & 1) * AT2_STGSZ);
        const int k0 = it * 64;

        float s[8][4];
#pragma unroll
        for (int nt = 0; nt < 8; nt++)
#pragma unroll
            for (int q = 0; q < 4; q++) s[nt][q] = 0.f;

#pragma unroll
        for (int ks = 0; ks < 4; ks++) {
            unsigned aqh[4], aql[4];
            int arow = m0 + (lane & 15);
            int acol = ks * 16 + (lane >> 4) * 8;
            ldsm4(aqh[0], aqh[1], aqh[2], aqh[3],
                  sbase + (AT2_QH + arow * 72 + acol) * 2);
            ldsm4(aql[0], aql[1], aql[2], aql[3],
                  sbase + (AT2_QL + arow * 72 + acol) * 2);
#pragma unroll
            for (int nt = 0; nt < 8; nt++) {
                int brow = nt * 8 + (lane & 7);
                int bcol = ks * 16 + ((lane >> 3) & 1) * 8;
                unsigned bkh[2], bkl[2];
                ldsm2(bkh[0], bkh[1], sbase + (so + AT2_KH + brow * 72 + bcol) * 2);
                ldsm2(bkl[0], bkl[1], sbase + (so + AT2_KL + brow * 72 + bcol) * 2);
                mma16816(s[nt], aqh, bkh);
                mma16816(s[nt], aqh, bkl);
                mma16816(s[nt], aql, bkh);
            }
        }

        int qa = q0 + m0 + g;
        int qb = qa + 8;
#pragma unroll
        for (int nt = 0; nt < 8; nt++) {
            int kj = k0 + nt * 8 + 2 * tk;
            s[nt][0] = s[nt][0] * 0.125f + slope * fmaxf((float)(qa - kj), 0.f);
            s[nt][1] = s[nt][1] * 0.125f + slope * fmaxf((float)(qa - kj - 1), 0.f);
            s[nt][2] = s[nt][2] * 0.125f + slope * fmaxf((float)(qb - kj), 0.f);
            s[nt][3] = s[nt][3] * 0.125f + slope * fmaxf((float)(qb - kj - 1), 0.f);
        }

        float mA = -1e30f, mB = -1e30f;
#pragma unroll
        for (int nt = 0; nt < 8; nt++) {
            mA = fmaxf(mA, fmaxf(s[nt][0], s[nt][1]));
            mB = fmaxf(mB, fmaxf(s[nt][2], s[nt][3]));
        }
        mA = fmaxf(mA, __shfl_xor_sync(0xffffffffu, mA, 1));
        mA = fmaxf(mA, __shfl_xor_sync(0xffffffffu, mA, 2));
        mB = fmaxf(mB, __shfl_xor_sync(0xffffffffu, mB, 1));
        mB = fmaxf(mB, __shfl_xor_sync(0xffffffffu, mB, 2));
        float mnA = fmaxf(mstA, mA);
        float mnB = fmaxf(mstB, mB);
        float alA = fexp(mstA - mnA);
        float alB = fexp(mstB - mnB);
        mstA = mnA;
        mstB = mnB;

        float rsA = 0.f, rsB = 0.f;
#pragma unroll
        for (int nt = 0; nt < 8; nt++) {
            float p0 = fexp(s[nt][0] - mstA);
            float p1 = fexp(s[nt][1] - mstA);
            float p2 = fexp(s[nt][2] - mstB);
            float p3 = fexp(s[nt][3] - mstB);
            s[nt][0] = p0; s[nt][1] = p1; s[nt][2] = p2; s[nt][3] = p3;
            rsA += p0 + p1;
            rsB += p2 + p3;
        }
        rsA += __shfl_xor_sync(0xffffffffu, rsA, 1);
        rsA += __shfl_xor_sync(0xffffffffu, rsA, 2);
        rsB += __shfl_xor_sync(0xffffffffu, rsB, 1);
        rsB += __shfl_xor_sync(0xffffffffu, rsB, 2);
        lstA = lstA * alA + rsA;
        lstB = lstB * alB + rsB;

#pragma unroll
        for (int dt = 0; dt < 8; dt++) {
            acc_o[dt][0] *= alA;
            acc_o[dt][1] *= alA;
            acc_o[dt][2] *= alB;
            acc_o[dt][3] *= alB;
        }

#pragma unroll
        for (int nt = 0; nt < 8; nt++) {
            int colb = nt * 8 + 2 * tk;
            ushort2 hA, lA, hB, lB;
            split2(s[nt][0], hA.x, lA.x);
            split2(s[nt][1], hA.y, lA.y);
            split2(s[nt][2], hB.x, lB.x);
            split2(s[nt][3], hB.y, lB.y);
            *(ushort2*)(sm2 + AT2_PH + (m0 + g) * 72 + colb) = hA;
            *(ushort2*)(sm2 + AT2_PL + (m0 + g) * 72 + colb) = lA;
            *(ushort2*)(sm2 + AT2_PH + (m0 + g + 8) * 72 + colb) = hB;
            *(ushort2*)(sm2 + AT2_PL + (m0 + g + 8) * 72 + colb) = lB;
        }
        __syncwarp();

#pragma unroll
        for (int kt = 0; kt < 4; kt++) {
            unsigned aph[4], apl[4];
            int prow = m0 + (lane & 15);
            int pcol = kt * 16 + (lane >> 4) * 8;
            ldsm4(aph[0], aph[1], aph[2], aph[3],
                  sbase + (AT2_PH + prow * 72 + pcol) * 2);
            ldsm4(apl[0], apl[1], apl[2], apl[3],
                  sbase + (AT2_PL + prow * 72 + pcol) * 2);
#pragma unroll
            for (int dt = 0; dt < 8; dt++) {
                int vrow = kt * 16 + (lane & 15);
                int vcol = dt * 8;
                unsigned bvh[2], bvl[2];
                ldsm2t(bvh[0], bvh[1], sbase + (so + AT2_VH + vrow * 72 + vcol) * 2);
                ldsm2t(bvl[0], bvl[1], sbase + (so + AT2_VL + vrow * 72 + vcol) * 2);
                mma16816(acc_o[dt], aph, bvh);
                mma16816(acc_o[dt], aph, bvl);
                mma16816(acc_o[dt], apl, bvh);
            }
        }
        __syncthreads();
        if (it + 2 < nc)
            at2_load_kv(sbase, it & 1, (it + 2) * 64, kh, kl, vh, vl, bh, tid);
    }

    float invA = 1.f / lstA;
    float invB = 1.f / lstB;
    int rowA = q0 + m0 + g;
    int rowB = rowA + 8;
#pragma unroll
    for (int dt = 0; dt < 8; dt++) {
        int col = h * HDd + dt * 8 + 2 * tk;
        long gA = ((long)(b * Ls + rowA)) * Ds + col;
        long gB = ((long)(b * Ls + rowB)) * Ds + col;
        ushort2 hA, lA, hB, lB;
        split2(acc_o[dt][0] * invA, hA.x, lA.x);
        split2(acc_o[dt][1] * invA, hA.y, lA.y);
        split2(acc_o[dt][2] * invB, hB.x, lB.x);
        split2(acc_o[dt][3] * invB, hB.y, lB.y);
        *(ushort2*)(Oh + gA) = hA;
        *(ushort2*)(Ol + gA) = lA;
        *(ushort2*)(Oh + gB) = hB;
        *(ushort2*)(Ol + gB) = lB;
    }
}

// ---------------- LayerNorm (single) ----------------
__global__ __launch_bounds__(256) void ln_kernel(
    const float* __restrict__ x, const float* __restrict__ g, const float* __restrict__ bb,
    const float* __restrict__ res, float* __restrict__ out,
    unsigned short* __restrict__ oh, unsigned short* __restrict__ ol)
{
    int row = blockIdx.x;
    const float* xr = x + (long)row * Ds;
    __shared__ float sx[Ds];
    __shared__ float sred[8];
    __shared__ float s_mean, s_rstd;
    int tid = threadIdx.x;

    float s = 0.f;
    for (int i = tid; i < Ds; i += 256) {
        float v = xr[i];
        sx[i] = v;
        s += v;
    }
#pragma unroll
    for (int o = 16; o > 0; o >>= 1) s += __shfl_down_sync(0xffffffffu, s, o);
    if ((tid & 31) == 0) sred[tid >> 5] = s;
    __syncthreads();
    if (tid == 0) {
        float t = 0.f;
        for (int i = 0; i < 8; i++) t += sred[i];
        s_mean = t / (float)Ds;
    }
    __syncthreads();
    float m = s_mean;
    float vs = 0.f;
    for (int i = tid; i < Ds; i += 256) {
        float d = sx[i] - m;
        vs += d * d;
    }
#pragma unroll
    for (int o = 16; o > 0; o >>= 1) vs += __shfl_down_sync(0xffffffffu, vs, o);
    if ((tid & 31) == 0) sred[tid >> 5] = vs;
    __syncthreads();
    if (tid == 0) {
        float t = 0.f;
        for (int i = 0; i < 8; i++) t += sred[i];
        s_rstd = rsqrtf(t / (float)Ds + EPSf);
    }
    __syncthreads();
    float rs = s_rstd;
    for (int i = tid; i < Ds; i += 256) {
        float v = (sx[i] - m) * rs * g[i] + bb[i];
        if (res) v += res[(long)row * Ds + i];
        long idx = (long)row * Ds + i;
        if (out) out[idx] = v;
        if (oh) {
            unsigned short hh, ll;
            split2(v, hh, ll);
            oh[idx] = hh;
            ol[idx] = ll;
        }
    }
}

// ---------------- fused double LN ----------------
__global__ __launch_bounds__(256) void ln_fused_kernel(
    const float* __restrict__ tgt2, const float* __restrict__ g1, const float* __restrict__ b1,
    const float* __restrict__ memory, float* __restrict__ mem_out,
    unsigned short* __restrict__ m_oh, unsigned short* __restrict__ m_ol,
    const float* __restrict__ g2, const float* __restrict__ b2,
    unsigned short* __restrict__ c_oh, unsigned short* __restrict__ c_ol)
{
    int row = blockIdx.x;
    __shared__ float sx[Ds];
    __shared__ float sred[8];
    __shared__ float s_mean, s_rstd;
    int tid = threadIdx.x;

    float s = 0.f;
    for (int i = tid; i < Ds; i += 256) {
        float v = tgt2[(long)row * Ds + i];
        sx[i] = v;
        s += v;
    }
#pragma unroll
    for (int o = 16; o > 0; o >>= 1) s += __shfl_down_sync(0xffffffffu, s, o);
    if ((tid & 31) == 0) sred[tid >> 5] = s;
    __syncthreads();
    if (tid == 0) {
        float t = 0.f;
        for (int i = 0; i < 8; i++) t += sred[i];
        s_mean = t / (float)Ds;
    }
    __syncthreads();
    float m = s_mean;
    float vs = 0.f;
    for (int i = tid; i < Ds; i += 256) {
        float d = sx[i] - m;
        vs += d * d;
    }
#pragma unroll
    for (int o = 16; o > 0; o >>= 1) vs += __shfl_down_sync(0xffffffffu, vs, o);
    if ((tid & 31) == 0) sred[tid >> 5] = vs;
    __syncthreads();
    if (tid == 0) {
        float t = 0.f;
        for (int i = 0; i < 8; i++) t += sred[i];
        s_rstd = rsqrtf(t / (float)Ds + EPSf);
    }
    __syncthreads();
    float rs = s_rstd;
    for (int i = tid; i < Ds; i += 256) {
        long idx = (long)row * Ds + i;
        float v = (sx[i] - m) * rs * g1[i] + b1[i] + memory[idx];
        sx[i] = v;
        mem_out[idx] = v;
        unsigned short hh, ll;
        split2(v, hh, ll);
        m_oh[idx] = hh;
        m_ol[idx] = ll;
    }
    __syncthreads();

    s = 0.f;
    for (int i = tid; i < Ds; i += 256) s += sx[i];
#pragma unroll
    for (int o = 16; o > 0; o >>= 1) s += __shfl_down_sync(0xffffffffu, s, o);
    if ((tid & 31) == 0) sred[tid >> 5] = s;
    __syncthreads();
    if (tid == 0) {
        float t = 0.f;
        for (int i = 0; i < 8; i++) t += sred[i];
        s_mean = t / (float)Ds;
    }
    __syncthreads();
    m = s_mean;
    vs = 0.f;
    for (int i = tid; i < Ds; i += 256) {
        float d = sx[i] - m;
        vs += d * d;
    }
#pragma unroll
    for (int o = 16; o > 0; o >>= 1) vs += __shfl_down_sync(0xffffffffu, vs, o);
    if ((tid & 31) == 0) sred[tid >> 5] = vs;
    __syncthreads();
    if (tid == 0) {
        float t = 0.f;
        for (int i = 0; i < 8; i++) t += sred[i];
        s_rstd = rsqrtf(t / (float)Ds + EPSf);
    }
    __syncthreads();
    rs = s_rstd;
    for (int i = tid; i < Ds; i += 256) {
        long idx = (long)row * Ds + i;
        float w = (sx[i] - m) * rs * g2[i] + b2[i];
        unsigned short hh, ll;
        split2(w, hh, ll);
        c_oh[idx] = hh;
        c_ol[idx] = ll;
    }
}

// ---------------- fused GLU + depthwise conv + bn + hardswish -> splits ----------------
__global__ __launch_bounds__(256) void glu_dwconv_kernel(
    const float* __restrict__ h2, const float* __restrict__ w, const float* __restrict__ wb,
    const float* __restrict__ bng, const float* __restrict__ bnb,
    unsigned short* __restrict__ oh, unsigned short* __restrict__ ol)
{
    __shared__ float sg[36 * 256];
    const int tid = threadIdx.x;
    const int d0 = blockIdx.x * 256;
    const int l0 = blockIdx.y * 32;
    const int b = blockIdx.z;
    const int d = d0 + tid;

#pragma unroll 4
    for (int j = 0; j < 36; j++) {
        int l = l0 + j - 2;
        float val = 0.f;
        if (l >= 0 && l < Ls) {
            long base = ((long)(b * Ls + l)) * (2 * Ds) + d;
            float a = h2[base];
            float gt = h2[base + Ds];
            val = a * (1.f / (1.f + __expf(-gt)));
        }
        sg[j * 256 + tid] = val;
    }
    __syncthreads();

    float w0 = w[d * 5 + 0], w1 = w[d * 5 + 1], w2 = w[d * 5 + 2];
    float w3 = w[d * 5 + 3], w4 = w[d * 5 + 4];
    float bs = rsqrtf(1.f + EPSf) * bng[d];
    float wbv = wb[d];
    float bnbv = bnb[d];
#pragma unroll 4
    for (int lr = 0; lr < 32; lr++) {
        float acc = w0 * sg[(lr + 4) * 256 + tid];
        acc = fmaf(w1, sg[(lr + 3) * 256 + tid], acc);
        acc = fmaf(w2, sg[(lr + 2) * 256 + tid], acc);
        acc = fmaf(w3, sg[(lr + 1) * 256 + tid], acc);
        acc = fmaf(w4, sg[(lr + 0) * 256 + tid], acc);
        float y = (acc + wbv) * bs + bnbv;
        float r6 = fminf(fmaxf(y + 3.f, 0.f), 6.f);
        float v = y * r6 * (1.f / 6.f);
        long idx = ((long)(b * Ls + l0 + lr)) * Ds + d;
        unsigned short hh, ll;
        split2(v, hh, ll);
        oh[idx] = hh;
        ol[idx] = ll;
    }
}

// ---------------- host helpers ----------------
static void run_splitT(const float* x, unsigned short* hiT, unsigned short* loT,
                       int R, int C, int batch)
{
    dim3 grid(C / 32, R / 32, batch);
    dim3 blk(32, 8);
    splitT_kernel<<<grid, blk>>>(x, hiT, loT, R, C, (long)R * C);
}

static void run_bgemm(const unsigned short* Ah, const unsigned short* Al,
                      const unsigned short* Bh, const unsigned short* Bl,
                      const float* bias, const float* addp, float* C,
                      unsigned short* oh, unsigned short* ol,
                      int M, int N, int K, int batch, long sB, long sC,
                      int bias_mode, int act)
{
    dim3 grid(N / 128, M / 128, batch);
    bgemm_kernel<<<grid, 256, BG_SMEM_BYTES>>>(Ah, Al, Bh, Bl, bias, addp, C,
                                               oh, ol, M, N, K, sB, sC, bias_mode, act);
}

extern "C" void kernel_launch(void* const* d_in, const int* in_sizes, int n_in,
                              void* d_out, int out_size)
{
    const float* p_memory = (const float*)d_in[0];
    const float* p_wq = (const float*)d_in[1];
    const float* p_bq = (const float*)d_in[2];
    const float* p_wk = (const float*)d_in[3];
    const float* p_bk = (const float*)d_in[4];
    const float* p_wv = (const float*)d_in[5];
    const float* p_bv = (const float*)d_in[6];
    const float* p_wo = (const float*)d_in[7];
    const float* p_bo = (const float*)d_in[8];
    const float* p_n1g = (const float*)d_in[9];
    const float* p_n1b = (const float*)d_in[10];
    const float* p_clng = (const float*)d_in[11];
    const float* p_clnb = (const float*)d_in[12];
    const float* p_pw1w = (const float*)d_in[13];
    const float* p_pw1b = (const float*)d_in[14];
    const float* p_dww = (const float*)d_in[15];
    const float* p_dwb = (const float*)d_in[16];
    const float* p_bng = (const float*)d_in[17];
    const float* p_bnb = (const float*)d_in[18];
    const float* p_pw2w = (const float*)d_in[19];
    const float* p_pw2b = (const float*)d_in[20];
    const float* p_projw = (const float*)d_in[21];
    const float* p_projb = (const float*)d_in[22];
    const float* p_proj2w = (const float*)d_in[23];
    const float* p_proj2b = (const float*)d_in[24];
    const float* p_lin1w = (const float*)d_in[25];
    const float* p_lin1b = (const float*)d_in[26];
    const float* p_lin2w = (const float*)d_in[27];
    const float* p_lin2b = (const float*)d_in[28];
    const float* p_n3g = (const float*)d_in[29];
    const float* p_n3b = (const float*)d_in[30];
    float* p_out = (float*)d_out;

    float* s_stage = 0;
    float* s_kst = 0;
    float* s_v = 0;
    float* s_tgt2 = 0;
    float* s_mem = 0;
    float* s_h2 = 0;
    float* s_conv = 0;
    float* s_mem2 = 0;
    float* s_sum = 0;
    unsigned short* s_ah = 0;
    unsigned short* s_al = 0;
    unsigned short* s_ch = 0;
    unsigned short* s_cl = 0;
    unsigned short* s_wh = 0;
    unsigned short* s_wl = 0;
    unsigned short* s_qh2 = 0;
    unsigned short* s_ql2 = 0;
    unsigned short* s_kh2 = 0;
    unsigned short* s_kl2 = 0;
    unsigned short* s_vh2 = 0;
    unsigned short* s_vl2 = 0;
    cudaGetSymbolAddress((void**)&s_stage, g_stage);
    cudaGetSymbolAddress((void**)&s_kst, g_kst);
    cudaGetSymbolAddress((void**)&s_v, g_v);
    cudaGetSymbolAddress((void**)&s_tgt2, g_tgt2);
    cudaGetSymbolAddress((void**)&s_mem, g_mem);
    cudaGetSymbolAddress((void**)&s_h2, g_h2);
    cudaGetSymbolAddress((void**)&s_conv, g_conv);
    cudaGetSymbolAddress((void**)&s_mem2, g_mem2);
    cudaGetSymbolAddress((void**)&s_sum, g_sum);
    cudaGetSymbolAddress((void**)&s_ah, g_ah);
    cudaGetSymbolAddress((void**)&s_al, g_al);
    cudaGetSymbolAddress((void**)&s_ch, g_ch);
    cudaGetSymbolAddress((void**)&s_cl, g_cl);
    cudaGetSymbolAddress((void**)&s_wh, g_wh);
    cudaGetSymbolAddress((void**)&s_wl, g_wl);
    cudaGetSymbolAddress((void**)&s_qh2, g_qh2);
    cudaGetSymbolAddress((void**)&s_ql2, g_ql2);
    cudaGetSymbolAddress((void**)&s_kh2, g_kh2);
    cudaGetSymbolAddress((void**)&s_kl2, g_kl2);
    cudaGetSymbolAddress((void**)&s_vh2, g_vh2);
    cudaGetSymbolAddress((void**)&s_vl2, g_vl2);

    cudaFuncSetAttribute(bgemm_kernel, cudaFuncAttributeMaxDynamicSharedMemorySize,
                         BG_SMEM_BYTES);
    cudaFuncSetAttribute(bgemm_brc_kernel, cudaFuncAttributeMaxDynamicSharedMemorySize,
                         BG_SMEM_BYTES);
    cudaFuncSetAttribute(attn2_kernel, cudaFuncAttributeMaxDynamicSharedMemorySize,
                         AT2_SMEM_BYTES);

    mega_split_kernel<<<20480, 256>>>(p_wq, p_wk, p_wv, p_wo, p_pw1w, p_pw2w,
                                      p_proj2w, p_lin1w, p_lin2w, p_memory,
                                      s_wh, s_wl, s_ah, s_al);
    run_splitT(p_projw, s_wh + OFF_PROJT, s_wl + OFF_PROJT, Ls, Ls, 1);

    run_bgemm(s_ah, s_al, s_wh + OFF_WQ, s_wl + OFF_WQ, p_bq, 0, s_stage, 0, 0,
              BLn, Ds, Ds, 1, 0, 0, 1, 0);
    run_bgemm(s_ah, s_al, s_wh + OFF_WK, s_wl + OFF_WK, p_bk, 0, s_kst, 0, 0,
              BLn, Ds, Ds, 1, 0, 0, 1, 0);
    run_bgemm(s_ah, s_al, s_wh + OFF_WV, s_wl + OFF_WV, p_bv, 0, s_v, 0, 0,
              BLn, Ds, Ds, 1, 0, 0, 1, 0);

    qkv_post_kernel<<<20480, 256>>>(s_stage, s_kst, s_v,
                                    s_qh2, s_ql2, s_kh2, s_kl2, s_vh2, s_vl2);

    {
        dim3 agrid(Ls / 128, Bb * Hh);
        attn2_kernel<<<agrid, 256, AT2_SMEM_BYTES>>>(
            s_qh2, s_ql2, s_kh2, s_kl2, s_vh2, s_vl2, s_ah, s_al);
    }

    run_bgemm(s_ah, s_al, s_wh + OFF_WO, s_wl + OFF_WO, p_bo, 0, s_tgt2, 0, 0,
              BLn, Ds, Ds, 1, 0, 0, 1, 0);

    ln_fused_kernel<<<BLn, 256>>>(s_tgt2, p_n1g, p_n1b, p_memory, s_mem,
                                  s_qh2, s_ql2, p_clng, p_clnb, s_ah, s_al);

    run_bgemm(s_ah, s_al, s_wh + OFF_PW1, s_wl + OFF_PW1, p_pw1b, 0, s_h2, 0, 0,
              BLn, 2 * Ds, Ds, 1, 0, 0, 1, 0);
    {
        dim3 gg(Ds / 256, Ls / 32, Bb);
        glu_dwconv_kernel<<<gg, 256>>>(s_h2, p_dww, p_dwb, p_bng, p_bnb, s_ah, s_al);
    }
    {
        dim3 grid(Ds / 128, BLn / 128);
        bgemm_brc_kernel<<<grid, 256, BG_SMEM_BYTES>>>(
            s_ah, s_al, s_wh + OFF_PW2, s_wl + OFF_PW2, p_pw2b, s_mem,
            s_conv, BLn, Ds, Ds);
    }

    run_bgemm(s_wh + OFF_PROJT, s_wl + OFF_PROJT, s_qh2, s_ql2, p_projb, 0, 0,
              s_ch, s_cl, Ls, Ds, Ls, Bb, (long)Ls * Ds, (long)Ls * Ds, 2, 0);
    run_bgemm(s_ch, s_cl, s_wh + OFF_PROJ2, s_wl + OFF_PROJ2, p_proj2b, s_conv,
              s_mem2, s_ah, s_al, BLn, Ds, Ds, 1, 0, 0, 1, 0);

    run_bgemm(s_ah, s_al, s_wh + OFF_LIN1, s_wl + OFF_LIN1, p_lin1b, 0, 0,
              s_ch, s_cl, BLn, FFs, Ds, 1, 0, 0, 1, 1);
    run_bgemm(s_ch, s_cl, s_wh + OFF_LIN2, s_wl + OFF_LIN2, p_lin2b, s_mem2,
              s_sum, 0, 0, BLn, Ds, FFs, 1, 0, 0, 1, 0);

    ln_kernel<<<BLn, 256>>>(s_sum, p_n3g, p_n3b, 0, p_out, 0, 0);
}

// round 17
// speedup vs baseline: 1.0477x; 1.0477x over previous
#include <cuda_runtime.h>
#include <cuda_bf16.h>
#include <math.h>

#define Bb 2
#define Ls 2048
#define Ds 1024
#define Hh 16
#define HDd 64
#define FFs 4096
#define BLn (Bb*Ls)
#define EPSf 1e-5f

// ---------------- scratch (static device memory) ----------------
__device__ float g_stage[BLn*Ds];
__device__ float g_kst[BLn*Ds];
__device__ float g_v[BLn*Ds];
__device__ float g_tgt2[BLn*Ds];
__device__ float g_mem[BLn*Ds];
__device__ float g_h2[BLn*2*Ds];
__device__ float g_conv[BLn*Ds];
__device__ float g_mem2[BLn*Ds];
__device__ float g_sum[BLn*Ds];
__device__ unsigned short g_ah[16777216];
__device__ unsigned short g_al[16777216];
__device__ unsigned short g_ch[16777216];
__device__ unsigned short g_cl[16777216];
#define OFF_WQ    0
#define OFF_WK    1048576
#define OFF_WV    2097152
#define OFF_WO    3145728
#define OFF_PW1   4194304
#define OFF_PW2   6291456
#define OFF_PROJ2 7340032
#define OFF_LIN1  8388608
#define OFF_LIN2  12582912
#define OFF_PROJT 16777216
__device__ unsigned short g_wh[20971520];
__device__ unsigned short g_wl[20971520];
__device__ unsigned short g_qh2[4194304];
__device__ unsigned short g_ql2[4194304];
__device__ unsigned short g_kh2[4194304];
__device__ unsigned short g_kl2[4194304];
__device__ unsigned short g_vh2[4194304];
__device__ unsigned short g_vl2[4194304];

// ---------------- helpers ----------------
__device__ __forceinline__ float fexp(float x)
{
    float t = x * 1.442695041f;
    t = fmaxf(t, -126.f);
    float fn = t + 12582912.f;
    int n = __float_as_int(fn) - 0x4B400000;
    float f = t - (fn - 12582912.f);
    float p = 1.33335581e-3f;
    p = fmaf(p, f, 9.61812910e-3f);
    p = fmaf(p, f, 5.55041087e-2f);
    p = fmaf(p, f, 2.40226507e-1f);
    p = fmaf(p, f, 6.93147180e-1f);
    p = fmaf(p, f, 1.0f);
    return __int_as_float((n + 127) << 23) * p;
}

__device__ __forceinline__ float gelu_exact(float v)
{
    return 0.5f * v * (1.f + erff(v * 0.70710678118654752f));
}

__device__ __forceinline__ void split2(float v, unsigned short& h, unsigned short& l)
{
    __nv_bfloat16 hb = __float2bfloat16_rn(v);
    h = __bfloat16_as_ushort(hb);
    l = __bfloat16_as_ushort(__float2bfloat16_rn(v - __bfloat162float(hb)));
}

// ---------------- mega split ----------------
__global__ __launch_bounds__(256) void mega_split_kernel(
    const float* __restrict__ wq, const float* __restrict__ wk,
    const float* __restrict__ wv, const float* __restrict__ wo,
    const float* __restrict__ pw1, const float* __restrict__ pw2,
    const float* __restrict__ proj2, const float* __restrict__ lin1,
    const float* __restrict__ lin2, const float* __restrict__ memory,
    unsigned short* __restrict__ wh, unsigned short* __restrict__ wl,
    unsigned short* __restrict__ ah, unsigned short* __restrict__ al)
{
    long i4 = (long)blockIdx.x * 256 + threadIdx.x;
    if (i4 >= 5242880L) return;
    const float* src;
    unsigned short* dh;
    unsigned short* dl;
    if (i4 < 4194304L) {
        const float* s;
        long bse;
        if (i4 < 262144L) { s = wq; bse = 0; }
        else if (i4 < 524288L) { s = wk; bse = 262144L; }
        else if (i4 < 786432L) { s = wv; bse = 524288L; }
        else if (i4 < 1048576L) { s = wo; bse = 786432L; }
        else if (i4 < 1572864L) { s = pw1; bse = 1048576L; }
        else if (i4 < 1835008L) { s = pw2; bse = 1572864L; }
        else if (i4 < 2097152L) { s = proj2; bse = 1835008L; }
        else if (i4 < 3145728L) { s = lin1; bse = 2097152L; }
        else { s = lin2; bse = 3145728L; }
        src = s + (i4 - bse) * 4;
        dh = wh + i4 * 4;
        dl = wl + i4 * 4;
    } else {
        long r = i4 - 4194304L;
        src = memory + r * 4;
        dh = ah + r * 4;
        dl = al + r * 4;
    }
    float4 v = *(const float4*)src;
    ushort4 hv, lv;
    split2(v.x, hv.x, lv.x);
    split2(v.y, hv.y, lv.y);
    split2(v.z, hv.z, lv.z);
    split2(v.w, hv.w, lv.w);
    *(ushort4*)dh = hv;
    *(ushort4*)dl = lv;
}

// ---------------- transpose + split ----------------
__global__ __launch_bounds__(256) void splitT_kernel(
    const float* __restrict__ in, unsigned short* __restrict__ hiT,
    unsigned short* __restrict__ loT, int R, int C, long sz)
{
    __shared__ float t[32][33];
    const float* inz = in + (long)blockIdx.z * sz;
    unsigned short* hz = hiT + (long)blockIdx.z * sz;
    unsigned short* lz = loT + (long)blockIdx.z * sz;
    int tx = threadIdx.x, ty = threadIdx.y;
    int x = blockIdx.x * 32 + tx;
    int y0 = blockIdx.y * 32;
#pragma unroll
    for (int j = 0; j < 32; j += 8)
        t[ty + j][tx] = inz[(long)(y0 + ty + j) * C + x];
    __syncthreads();
    int ox = blockIdx.y * 32 + tx;
    int oy0 = blockIdx.x * 32;
#pragma unroll
    for (int j = 0; j < 32; j += 8) {
        float val = t[tx][ty + j];
        unsigned short h, l;
        split2(val, h, l);
        hz[(long)(oy0 + ty + j) * R + ox] = h;
        lz[(long)(oy0 + ty + j) * R + ox] = l;
    }
}

// ---------------- mma helpers ----------------
__device__ __forceinline__ unsigned smem_u32(const void* p)
{
    return (unsigned)__cvta_generic_to_shared(p);
}
__device__ __forceinline__ void cp16(unsigned s, const void* g)
{
    asm volatile("cp.async.cg.shared.global [%0], [%1], 16;" :: "r"(s), "l"(g));
}
__device__ __forceinline__ void cp_commit()
{
    asm volatile("cp.async.commit_group;");
}
__device__ __forceinline__ void cp_wait1()
{
    asm volatile("cp.async.wait_group 1;");
}
__device__ __forceinline__ void cp_wait0()
{
    asm volatile("cp.async.wait_group 0;");
}
__device__ __forceinline__ void ldsm4(unsigned& r0, unsigned& r1, unsigned& r2, unsigned& r3, unsigned a)
{
    asm volatile("ldmatrix.sync.aligned.m8n8.x4.shared.b16 {%0,%1,%2,%3}, [%4];"
        : "=r"(r0), "=r"(r1), "=r"(r2), "=r"(r3) : "r"(a));
}
__device__ __forceinline__ void ldsm2(unsigned& r0, unsigned& r1, unsigned a)
{
    asm volatile("ldmatrix.sync.aligned.m8n8.x2.shared.b16 {%0,%1}, [%2];"
        : "=r"(r0), "=r"(r1) : "r"(a));
}
__device__ __forceinline__ void ldsm2t(unsigned& r0, unsigned& r1, unsigned a)
{
    asm volatile("ldmatrix.sync.aligned.m8n8.x2.trans.shared.b16 {%0,%1}, [%2];"
        : "=r"(r0), "=r"(r1) : "r"(a));
}
__device__ __forceinline__ void mma16816(float* d, const unsigned* a, const unsigned* b)
{
    asm volatile("mma.sync.aligned.m16n8k16.row.col.f32.bf16.bf16.f32 "
        "{%0,%1,%2,%3}, {%4,%5,%6,%7}, {%8,%9}, {%0,%1,%2,%3};"
        : "+f"(d[0]), "+f"(d[1]), "+f"(d[2]), "+f"(d[3])
        : "r"(a[0]), "r"(a[1]), "r"(a[2]), "r"(a[3]), "r"(b[0]), "r"(b[1]));
}

// ---------------- bf16-split tensor-core GEMM (R12 proven, UNTOUCHED) ----------------
#define LDA_P 40
#define LDB_P 136
#define OFF_AL (128*40)
#define OFF_BH (2*128*40)
#define OFF_BL (2*128*40 + 32*136)
#define STAGE_ELEMS (2*128*40 + 2*32*136)
#define BG_SMEM_BYTES (3*STAGE_ELEMS*2)

__device__ __forceinline__ void bg_load_chunk(
    unsigned short* st,
    const unsigned short* __restrict__ Ah, const unsigned short* __restrict__ Al,
    const unsigned short* __restrict__ Bh, const unsigned short* __restrict__ Bl,
    int K, int N, int bm, int bn, int k0, int tid)
{
    const int ar0 = tid >> 1;
    const int ac0 = (tid & 1) * 16;
    const int br0 = tid >> 4;
    const int bc0 = (tid & 15) * 8;
    {
        long ga = (long)(bm + ar0) * K + k0 + ac0;
        cp16(smem_u32(st + ar0 * LDA_P + ac0), Ah + ga);
        cp16(smem_u32(st + ar0 * LDA_P + ac0 + 8), Ah + ga + 8);
        cp16(smem_u32(st + OFF_AL + ar0 * LDA_P + ac0), Al + ga);
        cp16(smem_u32(st + OFF_AL + ar0 * LDA_P + ac0 + 8), Al + ga + 8);
    }
    {
        long gb0 = (long)(k0 + br0) * N + bn + bc0;
        long gb1 = (long)(k0 + br0 + 16) * N + bn + bc0;
        cp16(smem_u32(st + OFF_BH + br0 * LDB_P + bc0), Bh + gb0);
        cp16(smem_u32(st + OFF_BH + (br0 + 16) * LDB_P + bc0), Bh + gb1);
        cp16(smem_u32(st + OFF_BL + br0 * LDB_P + bc0), Bl + gb0);
        cp16(smem_u32(st + OFF_BL + (br0 + 16) * LDB_P + bc0), Bl + gb1);
    }
    cp_commit();
}

__global__ __launch_bounds__(256, 1) void bgemm_kernel(
    const unsigned short* __restrict__ Ah, const unsigned short* __restrict__ Al,
    const unsigned short* __restrict__ Bh, const unsigned short* __restrict__ Bl,
    const float* __restrict__ bias, const float* __restrict__ addp,
    float* __restrict__ C, unsigned short* __restrict__ oh,
    unsigned short* __restrict__ ol, int M, int N, int K,
    long sB, long sC, int bias_mode, int act)
{
    extern __shared__ unsigned short smem[];
    const int tid = threadIdx.x;
    const int lane = tid & 31;
    const int warp = tid >> 5;
    const int bm = blockIdx.y * 128;
    const int bn = blockIdx.x * 128;
    const unsigned short* Bhz = Bh + (long)blockIdx.z * sB;
    const unsigned short* Blz = Bl + (long)blockIdx.z * sB;
    float* Cz = C ? (C + (long)blockIdx.z * sC) : (float*)0;
    unsigned short* ohz = oh ? (oh + (long)blockIdx.z * sC) : (unsigned short*)0;
    unsigned short* olz = ol ? (ol + (long)blockIdx.z * sC) : (unsigned short*)0;
    const float* addz = addp ? (addp + (long)blockIdx.z * sC) : (const float*)0;
    const int m0 = (warp & 1) * 64;
    const int n0 = (warp >> 1) * 32;

    float acc[4][4][4];
#pragma unroll
    for (int mi = 0; mi < 4; mi++)
#pragma unroll
        for (int ni = 0; ni < 4; ni++)
#pragma unroll
            for (int qq = 0; qq < 4; qq++) acc[mi][ni][qq] = 0.f;

    const int nIter = K >> 5;

    bg_load_chunk(smem, Ah, Al, Bhz, Blz, K, N, bm, bn, 0, tid);
    if (nIter > 1)
        bg_load_chunk(smem + STAGE_ELEMS, Ah, Al, Bhz, Blz, K, N, bm, bn, 32, tid);

#pragma unroll 1
    for (int it = 0; it < nIter; ++it) {
        if (it + 1 < nIter) cp_wait1(); else cp_wait0();
        __syncthreads();

        unsigned short* cur = smem + (it % 3) * STAGE_ELEMS;
#pragma unroll
        for (int ks = 0; ks < 32; ks += 16) {
            unsigned afh[4][4], afl[4][4], bfh[4][2], bfl[4][2];
#pragma unroll
            for (int mi = 0; mi < 4; mi++) {
                int row = m0 + mi * 16 + (lane & 15);
                int col = ks + (lane >> 4) * 8;
                ldsm4(afh[mi][0], afh[mi][1], afh[mi][2], afh[mi][3],
                      smem_u32(cur + row * LDA_P + col));
                ldsm4(afl[mi][0], afl[mi][1], afl[mi][2], afl[mi][3],
                      smem_u32(cur + OFF_AL + row * LDA_P + col));
            }
#pragma unroll
            for (int ni = 0; ni < 4; ni++) {
                int row = ks + (lane & 15);
                int col = n0 + ni * 8;
                ldsm2t(bfh[ni][0], bfh[ni][1], smem_u32(cur + OFF_BH + row * LDB_P + col));
                ldsm2t(bfl[ni][0], bfl[ni][1], smem_u32(cur + OFF_BL + row * LDB_P + col));
            }
#pragma unroll
            for (int mi = 0; mi < 4; mi++) {
#pragma unroll
                for (int ni = 0; ni < 4; ni++) {
                    mma16816(acc[mi][ni], afh[mi], bfh[ni]);
                    mma16816(acc[mi][ni], afh[mi], bfl[ni]);
                    mma16816(acc[mi][ni], afl[mi], bfh[ni]);
                }
            }
        }
        if (it + 2 < nIter)
            bg_load_chunk(smem + ((it + 2) % 3) * STAGE_ELEMS,
                          Ah, Al, Bhz, Blz, K, N, bm, bn, (it + 2) << 5, tid);
    }

    const int r4 = lane >> 2;
    const int c2 = (lane & 3) * 2;
#pragma unroll
    for (int mi = 0; mi < 4; mi++) {
#pragma unroll
        for (int ni = 0; ni < 4; ni++) {
            int col = bn + n0 + ni * 8 + c2;
#pragma unroll
            for (int hf = 0; hf < 2; hf++) {
                int row = bm + m0 + mi * 16 + r4 + hf * 8;
                float v0 = acc[mi][ni][hf * 2 + 0];
                float v1 = acc[mi][ni][hf * 2 + 1];
                if (bias_mode == 1) { v0 += bias[col]; v1 += bias[col + 1]; }
                if (bias_mode == 2) { float bv = bias[row]; v0 += bv; v1 += bv; }
                if (addz) {
                    v0 += addz[(long)row * N + col];
                    v1 += addz[(long)row * N + col + 1];
                }
                if (act == 1) { v0 = gelu_exact(v0); v1 = gelu_exact(v1); }
                long idx = (long)row * N + col;
                if (Cz) {
                    float2 ov;
                    ov.x = v0; ov.y = v1;
                    *(float2*)(Cz + idx) = ov;
                }
                if (ohz) {
                    ushort2 hv, lv;
                    split2(v0, hv.x, lv.x);
                    split2(v1, hv.y, lv.y);
                    *(ushort2*)(ohz + idx) = hv;
                    *(ushort2*)(olz + idx) = lv;
                }
            }
        }
    }
}

// ---------------- clone with broadcast-row0 add (pw2 only) ----------------
__global__ __launch_bounds__(256, 1) void bgemm_brc_kernel(
    const unsigned short* __restrict__ Ah, const unsigned short* __restrict__ Al,
    const unsigned short* __restrict__ Bh, const unsigned short* __restrict__ Bl,
    const float* __restrict__ bias, const float* __restrict__ brc,
    float* __restrict__ C, int M, int N, int K)
{
    extern __shared__ unsigned short smem[];
    const int tid = threadIdx.x;
    const int lane = tid & 31;
    const int warp = tid >> 5;
    const int bm = blockIdx.y * 128;
    const int bn = blockIdx.x * 128;
    const int m0 = (warp & 1) * 64;
    const int n0 = (warp >> 1) * 32;

    float acc[4][4][4];
#pragma unroll
    for (int mi = 0; mi < 4; mi++)
#pragma unroll
        for (int ni = 0; ni < 4; ni++)
#pragma unroll
            for (int qq = 0; qq < 4; qq++) acc[mi][ni][qq] = 0.f;

    const int nIter = K >> 5;
    bg_load_chunk(smem, Ah, Al, Bh, Bl, K, N, bm, bn, 0, tid);
    if (nIter > 1)
        bg_load_chunk(smem + STAGE_ELEMS, Ah, Al, Bh, Bl, K, N, bm, bn, 32, tid);

#pragma unroll 1
    for (int it = 0; it < nIter; ++it) {
        if (it + 1 < nIter) cp_wait1(); else cp_wait0();
        __syncthreads();

        unsigned short* cur = smem + (it % 3) * STAGE_ELEMS;
#pragma unroll
        for (int ks = 0; ks < 32; ks += 16) {
            unsigned afh[4][4], afl[4][4], bfh[4][2], bfl[4][2];
#pragma unroll
            for (int mi = 0; mi < 4; mi++) {
                int row = m0 + mi * 16 + (lane & 15);
                int col = ks + (lane >> 4) * 8;
                ldsm4(afh[mi][0], afh[mi][1], afh[mi][2], afh[mi][3],
                      smem_u32(cur + row * LDA_P + col));
                ldsm4(afl[mi][0], afl[mi][1], afl[mi][2], afl[mi][3],
                      smem_u32(cur + OFF_AL + row * LDA_P + col));
            }
#pragma unroll
            for (int ni = 0; ni < 4; ni++) {
                int row = ks + (lane & 15);
                int col = n0 + ni * 8;
                ldsm2t(bfh[ni][0], bfh[ni][1], smem_u32(cur + OFF_BH + row * LDB_P + col));
                ldsm2t(bfl[ni][0], bfl[ni][1], smem_u32(cur + OFF_BL + row * LDB_P + col));
            }
#pragma unroll
            for (int mi = 0; mi < 4; mi++) {
#pragma unroll
                for (int ni = 0; ni < 4; ni++) {
                    mma16816(acc[mi][ni], afh[mi], bfh[ni]);
                    mma16816(acc[mi][ni], afh[mi], bfl[ni]);
                    mma16816(acc[mi][ni], afl[mi], bfh[ni]);
                }
            }
        }
        if (it + 2 < nIter)
            bg_load_chunk(smem + ((it + 2) % 3) * STAGE_ELEMS,
                          Ah, Al, Bh, Bl, K, N, bm, bn, (it + 2) << 5, tid);
    }

    const int r4 = lane >> 2;
    const int c2 = (lane & 3) * 2;
#pragma unroll
    for (int mi = 0; mi < 4; mi++) {
#pragma unroll
        for (int ni = 0; ni < 4; ni++) {
            int col = bn + n0 + ni * 8 + c2;
#pragma unroll
            for (int hf = 0; hf < 2; hf++) {
                int row = bm + m0 + mi * 16 + r4 + hf * 8;
                long bidx = (long)(row >> 11) * Ls * N + col;
                float v0 = acc[mi][ni][hf * 2 + 0] + bias[col] + brc[bidx];
                float v1 = acc[mi][ni][hf * 2 + 1] + bias[col + 1] + brc[bidx + 1];
                long idx = (long)row * N + col;
                float2 ov;
                ov.x = v0; ov.y = v1;
                *(float2*)(C + idx) = ov;
            }
        }
    }
}

// ---------------- rope helpers ----------------
__device__ __forceinline__ float rope_pval(int l, int m)
{
    int i = (m < 32) ? m : m - 32;
    float inv = powf(10000.f, -(float)(2 * i) / 64.f);
    float ang = (float)l * inv;
    return (m < 32) ? cosf(ang) : sinf(ang);
}

__device__ __forceinline__ void rope_body(const float* __restrict__ in,
    unsigned short* __restrict__ oh, unsigned short* __restrict__ ol, int idx)
{
    int j = idx & 31;
    int h = (idx >> 5) & 15;
    int bl = idx >> 9;
    int l = bl & (Ls - 1);
    int b = bl >> 11;
    long ibase = (long)bl * Ds + h * HDd;
    float xe = in[ibase + 2 * j];
    float xo = in[ibase + 2 * j + 1];
    float c = rope_pval(l, 2 * j);
    float s = rope_pval(l, 2 * j + 1);
    float y0 = xe * c - xo * s;
    float y1 = xe * s + xo * c;
    long obase = ((long)(b * Hh + h) * Ls + l) * HDd;
    unsigned short h0, l0, h1, l1;
    split2(y0, h0, l0);
    split2(y1, h1, l1);
    oh[obase + j] = h0;
    oh[obase + 32 + j] = h1;
    ol[obase + j] = l0;
    ol[obase + 32 + j] = l1;
}

__global__ __launch_bounds__(256) void qkv_post_kernel(
    const float* __restrict__ qs, const float* __restrict__ ks, const float* __restrict__ vs,
    unsigned short* __restrict__ qh, unsigned short* __restrict__ ql,
    unsigned short* __restrict__ kh, unsigned short* __restrict__ kl,
    unsigned short* __restrict__ vh, unsigned short* __restrict__ vl)
{
    int bid = blockIdx.x;
    int tid = threadIdx.x;
    if (bid < 8192) {
        rope_body(qs, qh, ql, bid * 256 + tid);
    } else if (bid < 16384) {
        rope_body(ks, kh, kl, (bid - 8192) * 256 + tid);
    } else {
        long idx4 = (long)(bid - 16384) * 256 + tid;
        int d4 = (int)(idx4 & 15);
        int h = (int)((idx4 >> 4) & 15);
        long l = (idx4 >> 8) & (Ls - 1);
        long b = idx4 >> 19;
        float4 v = *(const float4*)(vs + ((b * Ls + l) * Ds + h * HDd + d4 * 4));
        long o = ((b * Hh + h) * Ls + l) * HDd + d4 * 4;
        ushort4 hv, lv;
        split2(v.x, hv.x, lv.x);
        split2(v.y, hv.y, lv.y);
        split2(v.z, hv.z, lv.z);
        split2(v.w, hv.w, lv.w);
        *(ushort4*)(vh + o) = hv;
        *(ushort4*)(vl + o) = lv;
    }
}

// ---------------- tensor-core flash attention (3-stage KV pipeline) ----------------
#define AT2_QH 0
#define AT2_QL 9216
#define AT2_PH 18432
#define AT2_PL 27648
#define AT2_STG 36864
#define AT2_KH 0
#define AT2_KL 4608
#define AT2_VH 9216
#define AT2_VL 13824
#define AT2_STGSZ 18432
#define AT2_SMEM_BYTES ((36864 + 3*18432)*2)

__device__ __forceinline__ void at2_load_kv(
    unsigned sbase, int stage, int k0,
    const unsigned short* kh, const unsigned short* kl,
    const unsigned short* vh, const unsigned short* vl, int bh, int tid)
{
    unsigned so = (unsigned)(AT2_STG + stage * AT2_STGSZ);
#pragma unroll
    for (int i = 0; i < 2; i++) {
        int c = tid * 2 + i;
        int r = c >> 3;
        int cc = (c & 7) * 8;
        long g = ((long)bh * Ls + k0 + r) * HDd + cc;
        cp16(sbase + (so + AT2_KH + r * 72 + cc) * 2, kh + g);
        cp16(sbase + (so + AT2_KL + r * 72 + cc) * 2, kl + g);
        cp16(sbase + (so + AT2_VH + r * 72 + cc) * 2, vh + g);
        cp16(sbase + (so + AT2_VL + r * 72 + cc) * 2, vl + g);
    }
    cp_commit();
}

__global__ __launch_bounds__(256, 1) void attn2_kernel(
    const unsigned short* __restrict__ qh, const unsigned short* __restrict__ ql,
    const unsigned short* __restrict__ kh, const unsigned short* __restrict__ kl,
    const unsigned short* __restrict__ vh, const unsigned short* __restrict__ vl,
    unsigned short* __restrict__ Oh, unsigned short* __restrict__ Ol)
{
    extern __shared__ __align__(16) unsigned short sm2[];
    const int tid = threadIdx.x;
    const int lane = tid & 31;
    const int warp = tid >> 5;
    const int g = lane >> 2;
    const int tk = lane & 3;
    const int m0 = warp * 16;
    const int q0 = blockIdx.x * 128;
    const int bh = blockIdx.y;
    const int b = bh >> 4, h = bh & 15;
    const float slope = exp2f(-0.5f * (float)h);
    const unsigned sbase = smem_u32(sm2);

#pragma unroll
    for (int i = 0; i < 4; i++) {
        int t = tid + i * 256;
        int r = t >> 3;
        int cc = (t & 7) * 8;
        long gq = ((long)bh * Ls + q0 + r) * HDd + cc;
        cp16(sbase + (AT2_QH + r * 72 + cc) * 2, qh + gq);
        cp16(sbase + (AT2_QL + r * 72 + cc) * 2, ql + gq);
    }
    at2_load_kv(sbase, 0, 0, kh, kl, vh, vl, bh, tid);
    at2_load_kv(sbase, 1, 64, kh, kl, vh, vl, bh, tid);

    float acc_o[8][4];
#pragma unroll
    for (int dt = 0; dt < 8; dt++)
#pragma unroll
        for (int q = 0; q < 4; q++) acc_o[dt][q] = 0.f;
    float mstA = -1e30f, mstB = -1e30f, lstA = 0.f, lstB = 0.f;

    const int nc = Ls / 64;
#pragma unroll 1
    for (int it = 0; it < nc; ++it) {
        if (it < nc - 1) cp_wait1(); else cp_wait0();
        __syncthreads();
        unsigned so = (unsigned)(AT2_STG + (it % 3) * AT2_STGSZ);
        const int k0 = it * 64;

        float s[8][4];
#pragma unroll
        for (int nt = 0; nt < 8; nt++)
#pragma unroll
            for (int q = 0; q < 4; q++) s[nt][q] = 0.f;

#pragma unroll
        for (int ks = 0; ks < 4; ks++) {
            unsigned aqh[4], aql[4];
            int arow = m0 + (lane & 15);
            int acol = ks * 16 + (lane >> 4) * 8;
            ldsm4(aqh[0], aqh[1], aqh[2], aqh[3],
                  sbase + (AT2_QH + arow * 72 + acol) * 2);
            ldsm4(aql[0], aql[1], aql[2], aql[3],
                  sbase + (AT2_QL + arow * 72 + acol) * 2);
#pragma unroll
            for (int nt = 0; nt < 8; nt++) {
                int brow = nt * 8 + (lane & 7);
                int bcol = ks * 16 + ((lane >> 3) & 1) * 8;
                unsigned bkh[2], bkl[2];
                ldsm2(bkh[0], bkh[1], sbase + (so + AT2_KH + brow * 72 + bcol) * 2);
                ldsm2(bkl[0], bkl[1], sbase + (so + AT2_KL + brow * 72 + bcol) * 2);
                mma16816(s[nt], aqh, bkh);
                mma16816(s[nt], aqh, bkl);
                mma16816(s[nt], aql, bkh);
            }
        }

        int qa = q0 + m0 + g;
        int qb = qa + 8;
#pragma unroll
        for (int nt = 0; nt < 8; nt++) {
            int kj = k0 + nt * 8 + 2 * tk;
            s[nt][0] = s[nt][0] * 0.125f + slope * fmaxf((float)(qa - kj), 0.f);
            s[nt][1] = s[nt][1] * 0.125f + slope * fmaxf((float)(qa - kj - 1), 0.f);
            s[nt][2] = s[nt][2] * 0.125f + slope * fmaxf((float)(qb - kj), 0.f);
            s[nt][3] = s[nt][3] * 0.125f + slope * fmaxf((float)(qb - kj - 1), 0.f);
        }

        float mA = -1e30f, mB = -1e30f;
#pragma unroll
        for (int nt = 0; nt < 8; nt++) {
            mA = fmaxf(mA, fmaxf(s[nt][0], s[nt][1]));
            mB = fmaxf(mB, fmaxf(s[nt][2], s[nt][3]));
        }
        mA = fmaxf(mA, __shfl_xor_sync(0xffffffffu, mA, 1));
        mA = fmaxf(mA, __shfl_xor_sync(0xffffffffu, mA, 2));
        mB = fmaxf(mB, __shfl_xor_sync(0xffffffffu, mB, 1));
        mB = fmaxf(mB, __shfl_xor_sync(0xffffffffu, mB, 2));
        float mnA = fmaxf(mstA, mA);
        float mnB = fmaxf(mstB, mB);
        float alA = fexp(mstA - mnA);
        float alB = fexp(mstB - mnB);
        mstA = mnA;
        mstB = mnB;

        float rsA = 0.f, rsB = 0.f;
#pragma unroll
        for (int nt = 0; nt < 8; nt++) {
            float p0 = fexp(s[nt][0] - mstA);
            float p1 = fexp(s[nt][1] - mstA);
            float p2 = fexp(s[nt][2] - mstB);
            float p3 = fexp(s[nt][3] - mstB);
            s[nt][0] = p0; s[nt][1] = p1; s[nt][2] = p2; s[nt][3] = p3;
            rsA += p0 + p1;
            rsB += p2 + p3;
        }
        rsA += __shfl_xor_sync(0xffffffffu, rsA, 1);
        rsA += __shfl_xor_sync(0xffffffffu, rsA, 2);
        rsB += __shfl_xor_sync(0xffffffffu, rsB, 1);
        rsB += __shfl_xor_sync(0xffffffffu, rsB, 2);
        lstA = lstA * alA + rsA;
        lstB = lstB * alB + rsB;

#pragma unroll
        for (int dt = 0; dt < 8; dt++) {
            acc_o[dt][0] *= alA;
            acc_o[dt][1] *= alA;
            acc_o[dt][2] *= alB;
            acc_o[dt][3] *= alB;
        }

#pragma unroll
        for (int nt = 0; nt < 8; nt++) {
            int colb = nt * 8 + 2 * tk;
            ushort2 hA, lA, hB, lB;
            split2(s[nt][0], hA.x, lA.x);
            split2(s[nt][1], hA.y, lA.y);
            split2(s[nt][2], hB.x, lB.x);
            split2(s[nt][3], hB.y, lB.y);
            *(ushort2*)(sm2 + AT2_PH + (m0 + g) * 72 + colb) = hA;
            *(ushort2*)(sm2 + AT2_PL + (m0 + g) * 72 + colb) = lA;
            *(ushort2*)(sm2 + AT2_PH + (m0 + g + 8) * 72 + colb) = hB;
            *(ushort2*)(sm2 + AT2_PL + (m0 + g + 8) * 72 + colb) = lB;
        }
        __syncwarp();

#pragma unroll
        for (int kt = 0; kt < 4; kt++) {
            unsigned aph[4], apl[4];
            int prow = m0 + (lane & 15);
            int pcol = kt * 16 + (lane >> 4) * 8;
            ldsm4(aph[0], aph[1], aph[2], aph[3],
                  sbase + (AT2_PH + prow * 72 + pcol) * 2);
            ldsm4(apl[0], apl[1], apl[2], apl[3],
                  sbase + (AT2_PL + prow * 72 + pcol) * 2);
#pragma unroll
            for (int dt = 0; dt < 8; dt++) {
                int vrow = kt * 16 + (lane & 15);
                int vcol = dt * 8;
                unsigned bvh[2], bvl[2];
                ldsm2t(bvh[0], bvh[1], sbase + (so + AT2_VH + vrow * 72 + vcol) * 2);
                ldsm2t(bvl[0], bvl[1], sbase + (so + AT2_VL + vrow * 72 + vcol) * 2);
                mma16816(acc_o[dt], aph, bvh);
                mma16816(acc_o[dt], aph, bvl);
                mma16816(acc_o[dt], apl, bvh);
            }
        }
        // 3-stage ring: prefetch targets the stage consumed at iteration it-1,
        // already protected by this iteration's top-of-loop __syncthreads.
        if (it + 2 < nc)
            at2_load_kv(sbase, (it + 2) % 3, (it + 2) * 64, kh, kl, vh, vl, bh, tid);
    }

    float invA = 1.f / lstA;
    float invB = 1.f / lstB;
    int rowA = q0 + m0 + g;
    int rowB = rowA + 8;
#pragma unroll
    for (int dt = 0; dt < 8; dt++) {
        int col = h * HDd + dt * 8 + 2 * tk;
        long gA = ((long)(b * Ls + rowA)) * Ds + col;
        long gB = ((long)(b * Ls + rowB)) * Ds + col;
        ushort2 hA, lA, hB, lB;
        split2(acc_o[dt][0] * invA, hA.x, lA.x);
        split2(acc_o[dt][1] * invA, hA.y, lA.y);
        split2(acc_o[dt][2] * invB, hB.x, lB.x);
        split2(acc_o[dt][3] * invB, hB.y, lB.y);
        *(ushort2*)(Oh + gA) = hA;
        *(ushort2*)(Ol + gA) = lA;
        *(ushort2*)(Oh + gB) = hB;
        *(ushort2*)(Ol + gB) = lB;
    }
}

// ---------------- LayerNorm (single) ----------------
__global__ __launch_bounds__(256) void ln_kernel(
    const float* __restrict__ x, const float* __restrict__ g, const float* __restrict__ bb,
    const float* __restrict__ res, float* __restrict__ out,
    unsigned short* __restrict__ oh, unsigned short* __restrict__ ol)
{
    int row = blockIdx.x;
    const float* xr = x + (long)row * Ds;
    __shared__ float sx[Ds];
    __shared__ float sred[8];
    __shared__ float s_mean, s_rstd;
    int tid = threadIdx.x;

    float s = 0.f;
    for (int i = tid; i < Ds; i += 256) {
        float v = xr[i];
        sx[i] = v;
        s += v;
    }
#pragma unroll
    for (int o = 16; o > 0; o >>= 1) s += __shfl_down_sync(0xffffffffu, s, o);
    if ((tid & 31) == 0) sred[tid >> 5] = s;
    __syncthreads();
    if (tid == 0) {
        float t = 0.f;
        for (int i = 0; i < 8; i++) t += sred[i];
        s_mean = t / (float)Ds;
    }
    __syncthreads();
    float m = s_mean;
    float vs = 0.f;
    for (int i = tid; i < Ds; i += 256) {
        float d = sx[i] - m;
        vs += d * d;
    }
#pragma unroll
    for (int o = 16; o > 0; o >>= 1) vs += __shfl_down_sync(0xffffffffu, vs, o);
    if ((tid & 31) == 0) sred[tid >> 5] = vs;
    __syncthreads();
    if (tid == 0) {
        float t = 0.f;
        for (int i = 0; i < 8; i++) t += sred[i];
        s_rstd = rsqrtf(t / (float)Ds + EPSf);
    }
    __syncthreads();
    float rs = s_rstd;
    for (int i = tid; i < Ds; i += 256) {
        float v = (sx[i] - m) * rs * g[i] + bb[i];
        if (res) v += res[(long)row * Ds + i];
        long idx = (long)row * Ds + i;
        if (out) out[idx] = v;
        if (oh) {
            unsigned short hh, ll;
            split2(v, hh, ll);
            oh[idx] = hh;
            ol[idx] = ll;
        }
    }
}

// ---------------- fused double LN ----------------
__global__ __launch_bounds__(256) void ln_fused_kernel(
    const float* __restrict__ tgt2, const float* __restrict__ g1, const float* __restrict__ b1,
    const float* __restrict__ memory, float* __restrict__ mem_out,
    unsigned short* __restrict__ m_oh, unsigned short* __restrict__ m_ol,
    const float* __restrict__ g2, const float* __restrict__ b2,
    unsigned short* __restrict__ c_oh, unsigned short* __restrict__ c_ol)
{
    int row = blockIdx.x;
    __shared__ float sx[Ds];
    __shared__ float sred[8];
    __shared__ float s_mean, s_rstd;
    int tid = threadIdx.x;

    float s = 0.f;
    for (int i = tid; i < Ds; i += 256) {
        float v = tgt2[(long)row * Ds + i];
        sx[i] = v;
        s += v;
    }
#pragma unroll
    for (int o = 16; o > 0; o >>= 1) s += __shfl_down_sync(0xffffffffu, s, o);
    if ((tid & 31) == 0) sred[tid >> 5] = s;
    __syncthreads();
    if (tid == 0) {
        float t = 0.f;
        for (int i = 0; i < 8; i++) t += sred[i];
        s_mean = t / (float)Ds;
    }
    __syncthreads();
    float m = s_mean;
    float vs = 0.f;
    for (int i = tid; i < Ds; i += 256) {
        float d = sx[i] - m;
        vs += d * d;
    }
#pragma unroll
    for (int o = 16; o > 0; o >>= 1) vs += __shfl_down_sync(0xffffffffu, vs, o);
    if ((tid & 31) == 0) sred[tid >> 5] = vs;
    __syncthreads();
    if (tid == 0) {
        float t = 0.f;
        for (int i = 0; i < 8; i++) t += sred[i];
        s_rstd = rsqrtf(t / (float)Ds + EPSf);
    }
    __syncthreads();
    float rs = s_rstd;
    for (int i = tid; i < Ds; i += 256) {
        long idx = (long)row * Ds + i;
        float v = (sx[i] - m) * rs * g1[i] + b1[i] + memory[idx];
        sx[i] = v;
        mem_out[idx] = v;
        unsigned short hh, ll;
        split2(v, hh, ll);
        m_oh[idx] = hh;
        m_ol[idx] = ll;
    }
    __syncthreads();

    s = 0.f;
    for (int i = tid; i < Ds; i += 256) s += sx[i];
#pragma unroll
    for (int o = 16; o > 0; o >>= 1) s += __shfl_down_sync(0xffffffffu, s, o);
    if ((tid & 31) == 0) sred[tid >> 5] = s;
    __syncthreads();
    if (tid == 0) {
        float t = 0.f;
        for (int i = 0; i < 8; i++) t += sred[i];
        s_mean = t / (float)Ds;
    }
    __syncthreads();
    m = s_mean;
    vs = 0.f;
    for (int i = tid; i < Ds; i += 256) {
        float d = sx[i] - m;
        vs += d * d;
    }
#pragma unroll
    for (int o = 16; o > 0; o >>= 1) vs += __shfl_down_sync(0xffffffffu, vs, o);
    if ((tid & 31) == 0) sred[tid >> 5] = vs;
    __syncthreads();
    if (tid == 0) {
        float t = 0.f;
        for (int i = 0; i < 8; i++) t += sred[i];
        s_rstd = rsqrtf(t / (float)Ds + EPSf);
    }
    __syncthreads();
    rs = s_rstd;
    for (int i = tid; i < Ds; i += 256) {
        long idx = (long)row * Ds + i;
        float w = (sx[i] - m) * rs * g2[i] + b2[i];
        unsigned short hh, ll;
        split2(w, hh, ll);
        c_oh[idx] = hh;
        c_ol[idx] = ll;
    }
}

// ---------------- fused GLU + depthwise conv + bn + hardswish -> splits ----------------
__global__ __launch_bounds__(256) void glu_dwconv_kernel(
    const float* __restrict__ h2, const float* __restrict__ w, const float* __restrict__ wb,
    const float* __restrict__ bng, const float* __restrict__ bnb,
    unsigned short* __restrict__ oh, unsigned short* __restrict__ ol)
{
    __shared__ float sg[36 * 256];
    const int tid = threadIdx.x;
    const int d0 = blockIdx.x * 256;
    const int l0 = blockIdx.y * 32;
    const int b = blockIdx.z;
    const int d = d0 + tid;

#pragma unroll 4
    for (int j = 0; j < 36; j++) {
        int l = l0 + j - 2;
        float val = 0.f;
        if (l >= 0 && l < Ls) {
            long base = ((long)(b * Ls + l)) * (2 * Ds) + d;
            float a = h2[base];
            float gt = h2[base + Ds];
            val = a * (1.f / (1.f + __expf(-gt)));
        }
        sg[j * 256 + tid] = val;
    }
    __syncthreads();

    float w0 = w[d * 5 + 0], w1 = w[d * 5 + 1], w2 = w[d * 5 + 2];
    float w3 = w[d * 5 + 3], w4 = w[d * 5 + 4];
    float bs = rsqrtf(1.f + EPSf) * bng[d];
    float wbv = wb[d];
    float bnbv = bnb[d];
#pragma unroll 4
    for (int lr = 0; lr < 32; lr++) {
        float acc = w0 * sg[(lr + 4) * 256 + tid];
        acc = fmaf(w1, sg[(lr + 3) * 256 + tid], acc);
        acc = fmaf(w2, sg[(lr + 2) * 256 + tid], acc);
        acc = fmaf(w3, sg[(lr + 1) * 256 + tid], acc);
        acc = fmaf(w4, sg[(lr + 0) * 256 + tid], acc);
        float y = (acc + wbv) * bs + bnbv;
        float r6 = fminf(fmaxf(y + 3.f, 0.f), 6.f);
        float v = y * r6 * (1.f / 6.f);
        long idx = ((long)(b * Ls + l0 + lr)) * Ds + d;
        unsigned short hh, ll;
        split2(v, hh, ll);
        oh[idx] = hh;
        ol[idx] = ll;
    }
}

// ---------------- host helpers ----------------
static void run_splitT(const float* x, unsigned short* hiT, unsigned short* loT,
                       int R, int C, int batch)
{
    dim3 grid(C / 32, R / 32, batch);
    dim3 blk(32, 8);
    splitT_kernel<<<grid, blk>>>(x, hiT, loT, R, C, (long)R * C);
}

static void run_bgemm(const unsigned short* Ah, const unsigned short* Al,
                      const unsigned short* Bh, const unsigned short* Bl,
                      const float* bias, const float* addp, float* C,
                      unsigned short* oh, unsigned short* ol,
                      int M, int N, int K, int batch, long sB, long sC,
                      int bias_mode, int act)
{
    dim3 grid(N / 128, M / 128, batch);
    bgemm_kernel<<<grid, 256, BG_SMEM_BYTES>>>(Ah, Al, Bh, Bl, bias, addp, C,
                                               oh, ol, M, N, K, sB, sC, bias_mode, act);
}

extern "C" void kernel_launch(void* const* d_in, const int* in_sizes, int n_in,
                              void* d_out, int out_size)
{
    const float* p_memory = (const float*)d_in[0];
    const float* p_wq = (const float*)d_in[1];
    const float* p_bq = (const float*)d_in[2];
    const float* p_wk = (const float*)d_in[3];
    const float* p_bk = (const float*)d_in[4];
    const float* p_wv = (const float*)d_in[5];
    const float* p_bv = (const float*)d_in[6];
    const float* p_wo = (const float*)d_in[7];
    const float* p_bo = (const float*)d_in[8];
    const float* p_n1g = (const float*)d_in[9];
    const float* p_n1b = (const float*)d_in[10];
    const float* p_clng = (const float*)d_in[11];
    const float* p_clnb = (const float*)d_in[12];
    const float* p_pw1w = (const float*)d_in[13];
    const float* p_pw1b = (const float*)d_in[14];
    const float* p_dww = (const float*)d_in[15];
    const float* p_dwb = (const float*)d_in[16];
    const float* p_bng = (const float*)d_in[17];
    const float* p_bnb = (const float*)d_in[18];
    const float* p_pw2w = (const float*)d_in[19];
    const float* p_pw2b = (const float*)d_in[20];
    const float* p_projw = (const float*)d_in[21];
    const float* p_projb = (const float*)d_in[22];
    const float* p_proj2w = (const float*)d_in[23];
    const float* p_proj2b = (const float*)d_in[24];
    const float* p_lin1w = (const float*)d_in[25];
    const float* p_lin1b = (const float*)d_in[26];
    const float* p_lin2w = (const float*)d_in[27];
    const float* p_lin2b = (const float*)d_in[28];
    const float* p_n3g = (const float*)d_in[29];
    const float* p_n3b = (const float*)d_in[30];
    float* p_out = (float*)d_out;

    float* s_stage = 0;
    float* s_kst = 0;
    float* s_v = 0;
    float* s_tgt2 = 0;
    float* s_mem = 0;
    float* s_h2 = 0;
    float* s_conv = 0;
    float* s_mem2 = 0;
    float* s_sum = 0;
    unsigned short* s_ah = 0;
    unsigned short* s_al = 0;
    unsigned short* s_ch = 0;
    unsigned short* s_cl = 0;
    unsigned short* s_wh = 0;
    unsigned short* s_wl = 0;
    unsigned short* s_qh2 = 0;
    unsigned short* s_ql2 = 0;
    unsigned short* s_kh2 = 0;
    unsigned short* s_kl2 = 0;
    unsigned short* s_vh2 = 0;
    unsigned short* s_vl2 = 0;
    cudaGetSymbolAddress((void**)&s_stage, g_stage);
    cudaGetSymbolAddress((void**)&s_kst, g_kst);
    cudaGetSymbolAddress((void**)&s_v, g_v);
    cudaGetSymbolAddress((void**)&s_tgt2, g_tgt2);
    cudaGetSymbolAddress((void**)&s_mem, g_mem);
    cudaGetSymbolAddress((void**)&s_h2, g_h2);
    cudaGetSymbolAddress((void**)&s_conv, g_conv);
    cudaGetSymbolAddress((void**)&s_mem2, g_mem2);
    cudaGetSymbolAddress((void**)&s_sum, g_sum);
    cudaGetSymbolAddress((void**)&s_ah, g_ah);
    cudaGetSymbolAddress((void**)&s_al, g_al);
    cudaGetSymbolAddress((void**)&s_ch, g_ch);
    cudaGetSymbolAddress((void**)&s_cl, g_cl);
    cudaGetSymbolAddress((void**)&s_wh, g_wh);
    cudaGetSymbolAddress((void**)&s_wl, g_wl);
    cudaGetSymbolAddress((void**)&s_qh2, g_qh2);
    cudaGetSymbolAddress((void**)&s_ql2, g_ql2);
    cudaGetSymbolAddress((void**)&s_kh2, g_kh2);
    cudaGetSymbolAddress((void**)&s_kl2, g_kl2);
    cudaGetSymbolAddress((void**)&s_vh2, g_vh2);
    cudaGetSymbolAddress((void**)&s_vl2, g_vl2);

    cudaFuncSetAttribute(bgemm_kernel, cudaFuncAttributeMaxDynamicSharedMemorySize,
                         BG_SMEM_BYTES);
    cudaFuncSetAttribute(bgemm_brc_kernel, cudaFuncAttributeMaxDynamicSharedMemorySize,
                         BG_SMEM_BYTES);
    cudaFuncSetAttribute(attn2_kernel, cudaFuncAttributeMaxDynamicSharedMemorySize,
                         AT2_SMEM_BYTES);

    mega_split_kernel<<<20480, 256>>>(p_wq, p_wk, p_wv, p_wo, p_pw1w, p_pw2w,
                                      p_proj2w, p_lin1w, p_lin2w, p_memory,
                                      s_wh, s_wl, s_ah, s_al);
    run_splitT(p_projw, s_wh + OFF_PROJT, s_wl + OFF_PROJT, Ls, Ls, 1);

    run_bgemm(s_ah, s_al, s_wh + OFF_WQ, s_wl + OFF_WQ, p_bq, 0, s_stage, 0, 0,
              BLn, Ds, Ds, 1, 0, 0, 1, 0);
    run_bgemm(s_ah, s_al, s_wh + OFF_WK, s_wl + OFF_WK, p_bk, 0, s_kst, 0, 0,
              BLn, Ds, Ds, 1, 0, 0, 1, 0);
    run_bgemm(s_ah, s_al, s_wh + OFF_WV, s_wl + OFF_WV, p_bv, 0, s_v, 0, 0,
              BLn, Ds, Ds, 1, 0, 0, 1, 0);

    qkv_post_kernel<<<20480, 256>>>(s_stage, s_kst, s_v,
                                    s_qh2, s_ql2, s_kh2, s_kl2, s_vh2, s_vl2);

    {
        dim3 agrid(Ls / 128, Bb * Hh);
        attn2_kernel<<<agrid, 256, AT2_SMEM_BYTES>>>(
            s_qh2, s_ql2, s_kh2, s_kl2, s_vh2, s_vl2, s_ah, s_al);
    }

    run_bgemm(s_ah, s_al, s_wh + OFF_WO, s_wl + OFF_WO, p_bo, 0, s_tgt2, 0, 0,
              BLn, Ds, Ds, 1, 0, 0, 1, 0);

    ln_fused_kernel<<<BLn, 256>>>(s_tgt2, p_n1g, p_n1b, p_memory, s_mem,
                                  s_qh2, s_ql2, p_clng, p_clnb, s_ah, s_al);

    run_bgemm(s_ah, s_al, s_wh + OFF_PW1, s_wl + OFF_PW1, p_pw1b, 0, s_h2, 0, 0,
              BLn, 2 * Ds, Ds, 1, 0, 0, 1, 0);
    {
        dim3 gg(Ds / 256, Ls / 32, Bb);
        glu_dwconv_kernel<<<gg, 256>>>(s_h2, p_dww, p_dwb, p_bng, p_bnb, s_ah, s_al);
    }
    {
        dim3 grid(Ds / 128, BLn / 128);
        bgemm_brc_kernel<<<grid, 256, BG_SMEM_BYTES>>>(
            s_ah, s_al, s_wh + OFF_PW2, s_wl + OFF_PW2, p_pw2b, s_mem,
            s_conv, BLn, Ds, Ds);
    }

    run_bgemm(s_wh + OFF_PROJT, s_wl + OFF_PROJT, s_qh2, s_ql2, p_projb, 0, 0,
              s_ch, s_cl, Ls, Ds, Ls, Bb, (long)Ls * Ds, (long)Ls * Ds, 2, 0);
    run_bgemm(s_ch, s_cl, s_wh + OFF_PROJ2, s_wl + OFF_PROJ2, p_proj2b, s_conv,
              s_mem2, s_ah, s_al, BLn, Ds, Ds, 1, 0, 0, 1, 0);

    run_bgemm(s_ah, s_al, s_wh + OFF_LIN1, s_wl + OFF_LIN1, p_lin1b, 0, 0,
              s_ch, s_cl, BLn, FFs, Ds, 1, 0, 0, 1, 1);
    run_bgemm(s_ch, s_cl, s_wh + OFF_LIN2, s_wl + OFF_LIN2, p_lin2b, s_mem2,
              s_sum, 0, 0, BLn, Ds, FFs, 1, 0, 0, 1, 0);

    ln_kernel<<<BLn, 256>>>(s_sum, p_n3g, p_n3b, 0, p_out, 0, 0);
}